// round 7
// baseline (speedup 1.0000x reference)
#include <cuda_runtime.h>
#include <math.h>
#include <stdint.h>

#define S 2048
#define BATCH 2
#define D 1024
#define H 16
#define FFN_DIM 4096
#define T (S*BATCH)
#define NEGV -1e9f

// ---------------- scratch (device globals; no allocation allowed) ----------------
__device__ float g_q[(size_t)T*D];
__device__ float g_k[(size_t)T*D];
__device__ float g_v[(size_t)T*D];
__device__ float g_ao[(size_t)T*D];
__device__ float g_x1[(size_t)T*D];
__device__ float g_x1r[(size_t)T*D];
__device__ float g_y[(size_t)T*D];
__device__ float g_h[(size_t)T*FFN_DIM];
__device__ float g_attn[(size_t)BATCH*H*S*S];   // fallback probs target only
__device__ float g_xr[(size_t)T*D];
__device__ float g_wqt[(size_t)D*D];
__device__ float g_wkt[(size_t)D*D];
__device__ float g_wvt[(size_t)D*D];
__device__ float g_wot[(size_t)D*D];
__device__ float g_w1t[(size_t)D*FFN_DIM];
__device__ float g_w2t[(size_t)D*FFN_DIM];

// ---------------- helpers ----------------
__device__ __forceinline__ float to_tf32(float x) {
    uint32_t u;
    asm("cvt.rna.tf32.f32 %0, %1;" : "=r"(u) : "f"(x));
    return __uint_as_float(u);
}

__device__ __forceinline__ void mma8(float* c, const uint32_t* a, const uint32_t* b) {
    asm("mma.sync.aligned.m16n8k8.row.col.f32.tf32.tf32.f32 "
        "{%0,%1,%2,%3},{%4,%5,%6,%7},{%8,%9},{%0,%1,%2,%3};"
        : "+f"(c[0]), "+f"(c[1]), "+f"(c[2]), "+f"(c[3])
        : "r"(a[0]), "r"(a[1]), "r"(a[2]), "r"(a[3]),
          "r"(b[0]), "r"(b[1]));
}

__device__ __forceinline__ void ldsm4(uint32_t& r0, uint32_t& r1, uint32_t& r2, uint32_t& r3,
                                      uint32_t addr) {
    asm volatile("ldmatrix.sync.aligned.m8n8.x4.shared.b16 {%0,%1,%2,%3}, [%4];"
                 : "=r"(r0), "=r"(r1), "=r"(r2), "=r"(r3) : "r"(addr));
}

__device__ __forceinline__ void cpasync16(uint32_t dst, const float* src) {
    asm volatile("cp.async.cg.shared.global [%0], [%1], 16;" :: "r"(dst), "l"(src));
}

__device__ __forceinline__ int chidx(int row, int kq) {
    return (row * 4 + (kq ^ ((row >> 1) & 3))) * 4;
}

__device__ __forceinline__ float gelu(float v) {
    return 0.5f * v * (1.0f + erff(v * 0.70710678118654752f));
}

// =====================================================================
// cp.async 3-stage tf32 GEMM (round-5, unchanged).
// =====================================================================
template<int EPI, int ZMODE, bool ROUND>
__global__ __launch_bounds__(256, 2) void mma_gemm_ca(
    const float* __restrict__ A, long long lda,
    const float* __restrict__ Bg, long long ldb,
    const float* __restrict__ bias,
    float* __restrict__ C, long long ldc,
    int K, float scale)
{
    constexpr int MT = 4, NT = 4, STG = 3;

    __shared__ float sA[STG][2048];
    __shared__ float sB[STG][2048];

    const int tid  = threadIdx.x;
    const int lane = tid & 31;
    const int w    = tid >> 5;
    const int wm   = w & 1;
    const int wn   = w >> 1;
    const int m0   = blockIdx.y * 128;
    const int n0   = blockIdx.x * 128;
    const int z    = blockIdx.z;

    if (ZMODE == 1) {
        int hoff = (z >> 4) * D + (z & 15) * 64;
        A  += hoff;
        Bg += hoff;
        C  += (size_t)z * S * S;
    }

    float acc[MT][NT][4] = {};
    const int ntiles = K >> 4;

    const int fm = lane >> 3;
    const int fj = lane & 7;
    const int aRowBase = wm * 64 + (fm & 1) * 8 + fj;
    const int aKqOff   = fm >> 1;
    const int bTileOff = fm >> 1;
    const int bKqOff   = fm & 1;

    const uint32_t sA0 = (uint32_t)__cvta_generic_to_shared(&sA[0][0]);
    const uint32_t sB0 = (uint32_t)__cvta_generic_to_shared(&sB[0][0]);

    const int sRow0 = tid >> 2,  sKq = tid & 3;
    const int sRow1 = sRow0 + 64;

    auto issue = [&](int t) {
        if (t < ntiles) {
            const int buf = t % STG;
            const int k0  = t << 4;
            const uint32_t aBase = sA0 + buf * 8192;
            const uint32_t bBase = sB0 + buf * 8192;
            cpasync16(aBase + (uint32_t)(chidx(sRow0, sKq) * 4),
                      A + (size_t)(m0 + sRow0) * lda + k0 + sKq * 4);
            cpasync16(aBase + (uint32_t)(chidx(sRow1, sKq) * 4),
                      A + (size_t)(m0 + sRow1) * lda + k0 + sKq * 4);
            cpasync16(bBase + (uint32_t)(chidx(sRow0, sKq) * 4),
                      Bg + (size_t)(n0 + sRow0) * ldb + k0 + sKq * 4);
            cpasync16(bBase + (uint32_t)(chidx(sRow1, sKq) * 4),
                      Bg + (size_t)(n0 + sRow1) * ldb + k0 + sKq * 4);
        }
        asm volatile("cp.async.commit_group;");
    };

    auto compute = [&](int buf) {
        const uint32_t aBase = sA0 + buf * 8192;
        const uint32_t bBase = sB0 + buf * 8192;
        #pragma unroll
        for (int ks = 0; ks < 2; ks++) {
            uint32_t a[MT][4];
            uint32_t b[NT][2];
            const int akq = ks * 2 + aKqOff;
            const int bkq = ks * 2 + bKqOff;
            #pragma unroll
            for (int i = 0; i < MT; i++) {
                uint32_t addr = aBase + (uint32_t)(chidx(aRowBase + i * 16, akq) * 4);
                ldsm4(a[i][0], a[i][1], a[i][2], a[i][3], addr);
            }
            #pragma unroll
            for (int j2 = 0; j2 < NT; j2 += 2) {
                int tile = wn * NT + j2 + bTileOff;
                uint32_t addr = bBase + (uint32_t)(chidx(tile * 8 + fj, bkq) * 4);
                ldsm4(b[j2][0], b[j2][1], b[j2 + 1][0], b[j2 + 1][1], addr);
            }
            #pragma unroll
            for (int i = 0; i < MT; i++)
                #pragma unroll
                for (int j = 0; j < NT; j++)
                    mma8(acc[i][j], a[i], b[j]);
        }
    };

    issue(0);
    issue(1);
    for (int t = 0; t < ntiles; t++) {
        asm volatile("cp.async.wait_group 1;");
        __syncthreads();
        issue(t + 2);
        compute(t % STG);
    }

    #pragma unroll
    for (int i = 0; i < MT; i++) {
        int r0 = m0 + wm * 64 + i * 16 + (lane >> 2);
        #pragma unroll
        for (int j = 0; j < NT; j++) {
            int col = n0 + wn * 32 + j * 8 + ((lane & 3) << 1);
            float bx = 0.f, by = 0.f;
            if (EPI != 3) {
                float2 bb = *(const float2*)&bias[col];
                bx = bb.x; by = bb.y;
            }
            float v0 = acc[i][j][0] + bx, v1 = acc[i][j][1] + by;
            float v2 = acc[i][j][2] + bx, v3 = acc[i][j][3] + by;
            if (EPI == 1) { v0 *= scale; v1 *= scale; v2 *= scale; v3 *= scale; }
            if (EPI == 2) { v0 = gelu(v0); v1 = gelu(v1); v2 = gelu(v2); v3 = gelu(v3); }
            if (ROUND) {
                v0 = to_tf32(v0); v1 = to_tf32(v1);
                v2 = to_tf32(v2); v3 = to_tf32(v3);
            }
            *(float2*)&C[(size_t)r0 * ldc + col]       = make_float2(v0, v1);
            *(float2*)&C[(size_t)(r0 + 8) * ldc + col] = make_float2(v2, v3);
        }
    }
}

// =====================================================================
// Fused attention: QK^T + mask + softmax + PV, flash-style with recompute.
// THREE-stage K/V ring buffers (race fix vs round 6).
// float offsets: sQ 0 (8192) | sK 8192 (3x4096) | sV 20480 (3x4608)
//                sP 34304 (8192) | tr 42496 (512) | m 43008 | s 43136 | bc 43264
// =====================================================================
#define AF_SMEM_FLOATS 43392
#define AF_SMEM_BYTES (AF_SMEM_FLOATS * 4)

__global__ __launch_bounds__(256, 1) void attn_fused(
    const float* __restrict__ qg, const float* __restrict__ kg,
    const float* __restrict__ vg, const unsigned char* __restrict__ mask,
    float* __restrict__ probs, float* __restrict__ aog)
{
    extern __shared__ float sm[];
    const int tid  = threadIdx.x;
    const int lane = tid & 31;
    const int w    = tid >> 5;
    const int wm   = w & 1;
    const int wn   = w >> 1;
    const int q0   = blockIdx.x * 128;
    const int z    = blockIdx.y;
    const int b    = z >> 4, hh = z & 15;
    const long long ld = (long long)BATCH * D;

    const float* Q = qg + (size_t)b * D + hh * 64;
    const float* K = kg + (size_t)b * D + hh * 64;
    const float* V = vg + (size_t)b * D + hh * 64;
    float* P  = probs + (size_t)z * S * S;
    float* AO = aog + (size_t)b * D + hh * 64;
    const unsigned char* MK = mask + (size_t)b * S;

    const uint32_t smb = (uint32_t)__cvta_generic_to_shared(sm);
    float* sV   = sm + 20480;
    float* sP   = sm + 34304;
    float* tr   = sm + 42496;
    float* mrow = sm + 43008;
    float* srow = sm + 43136;
    float* bc   = sm + 43264;

    const int fm = lane >> 3;
    const int fj = lane & 7;
    const int aRowBase = wm * 64 + (fm & 1) * 8 + fj;
    const int aKqOff   = fm >> 1;
    const int bTileOff = fm >> 1;
    const int bKqOff   = fm & 1;

    if (tid < 128) { mrow[tid] = -1e30f; srow[tid] = 0.0f; }

    // ---- stage Q once (folded into first K commit group) ----
    #pragma unroll
    for (int u = 0; u < 8; u++) {
        int c = tid + u * 256;
        int row = c >> 4, kqg = c & 15;
        cpasync16(smb + (uint32_t)(((kqg >> 2) * 2048 + chidx(row, kqg & 3)) * 4),
                  Q + (size_t)(q0 + row) * ld + kqg * 4);
    }

    auto issueK = [&](int it) {
        if (it < 32) {
            const int buf = it % 3;
            const int key0 = it * 64;
            const uint32_t kb = smb + (uint32_t)((8192 + buf * 4096) * 4);
            #pragma unroll
            for (int u = 0; u < 4; u++) {
                int c = tid + u * 256;
                int key = c >> 4, kqg = c & 15;
                cpasync16(kb + (uint32_t)(((kqg >> 2) * 1024 + chidx(key, kqg & 3)) * 4),
                          K + (size_t)(key0 + key) * ld + kqg * 4);
            }
        }
        asm volatile("cp.async.commit_group;");
    };
    auto issueKV = [&](int it) {
        if (it < 32) {
            const int buf = it % 3;
            const int key0 = it * 64;
            const uint32_t kb = smb + (uint32_t)((8192 + buf * 4096) * 4);
            const uint32_t vb = smb + (uint32_t)((20480 + buf * 4608) * 4);
            #pragma unroll
            for (int u = 0; u < 4; u++) {
                int c = tid + u * 256;
                int key = c >> 4, kqg = c & 15;
                cpasync16(kb + (uint32_t)(((kqg >> 2) * 1024 + chidx(key, kqg & 3)) * 4),
                          K + (size_t)(key0 + key) * ld + kqg * 4);
            }
            #pragma unroll
            for (int u = 0; u < 4; u++) {
                int c = tid + u * 256;
                int key = c >> 4, dg = c & 15;
                int wk = ((key >> 2) & 3) << 3;
                cpasync16(vb + (uint32_t)((key * 72 + ((dg * 4) ^ wk)) * 4),
                          V + (size_t)(key0 + key) * ld + dg * 4);
            }
        }
        asm volatile("cp.async.commit_group;");
    };

    auto score = [&](int buf, float (&acc)[4][2][4]) {
        #pragma unroll
        for (int i = 0; i < 4; i++)
            #pragma unroll
            for (int j = 0; j < 2; j++)
                #pragma unroll
                for (int c = 0; c < 4; c++) acc[i][j][c] = 0.f;
        const uint32_t kb = smb + (uint32_t)((8192 + buf * 4096) * 4);
        #pragma unroll
        for (int st = 0; st < 4; st++) {
            #pragma unroll
            for (int ks = 0; ks < 2; ks++) {
                uint32_t a[4][4];
                uint32_t bfr[2][2];
                const int akq = ks * 2 + aKqOff;
                const int bkq = ks * 2 + bKqOff;
                #pragma unroll
                for (int i = 0; i < 4; i++) {
                    uint32_t addr = smb + (uint32_t)((st * 2048 +
                                      chidx(aRowBase + i * 16, akq)) * 4);
                    ldsm4(a[i][0], a[i][1], a[i][2], a[i][3], addr);
                }
                {
                    int tile = wn * 2 + bTileOff;
                    uint32_t addr = kb + (uint32_t)((st * 1024 +
                                      chidx(tile * 8 + fj, bkq)) * 4);
                    ldsm4(bfr[0][0], bfr[0][1], bfr[1][0], bfr[1][1], addr);
                }
                #pragma unroll
                for (int i = 0; i < 4; i++)
                    #pragma unroll
                    for (int j = 0; j < 2; j++)
                        mma8(acc[i][j], a[i], bfr[j]);
            }
        }
    };

    float acc[4][2][4];

    // ================= PASS A: row stats =================
    issueK(0);
    issueK(1);
    for (int it = 0; it < 32; it++) {
        asm volatile("cp.async.wait_group 1;");
        __syncthreads();
        issueK(it + 2);
        score(it % 3, acc);

        const int key0 = it * 64;
        float mk4[2][2];
        #pragma unroll
        for (int j = 0; j < 2; j++)
            #pragma unroll
            for (int c = 0; c < 2; c++)
                mk4[j][c] = MK[key0 + wn * 16 + j * 8 + ((lane & 3) << 1) + c] ? NEGV : 0.f;

        float lm[4][2];
        #pragma unroll
        for (int i = 0; i < 4; i++)
            #pragma unroll
            for (int h = 0; h < 2; h++) {
                float v0 = acc[i][0][2*h]   + mk4[0][0];
                float v1 = acc[i][0][2*h+1] + mk4[0][1];
                float v2 = acc[i][1][2*h]   + mk4[1][0];
                float v3 = acc[i][1][2*h+1] + mk4[1][1];
                lm[i][h] = fmaxf(fmaxf(v0, v1), fmaxf(v2, v3));
            }
        #pragma unroll
        for (int i = 0; i < 4; i++)
            #pragma unroll
            for (int h = 0; h < 2; h++) {
                lm[i][h] = fmaxf(lm[i][h], __shfl_xor_sync(0xffffffffu, lm[i][h], 1));
                lm[i][h] = fmaxf(lm[i][h], __shfl_xor_sync(0xffffffffu, lm[i][h], 2));
            }
        if ((lane & 3) == 0) {
            #pragma unroll
            for (int i = 0; i < 4; i++)
                #pragma unroll
                for (int h = 0; h < 2; h++)
                    tr[wn * 128 + wm * 64 + i * 16 + (lane >> 2) + h * 8] = lm[i][h];
        }
        __syncthreads();
        if (tid < 128) {
            float mt = fmaxf(fmaxf(tr[tid], tr[128 + tid]),
                             fmaxf(tr[256 + tid], tr[384 + tid]));
            float mo = mrow[tid];
            float mn = fmaxf(mo, mt);
            bc[tid] = mn;
            srow[tid] *= __expf(mo - mn);
            mrow[tid] = mn;
        }
        __syncthreads();
        float ls[4][2];
        #pragma unroll
        for (int i = 0; i < 4; i++)
            #pragma unroll
            for (int h = 0; h < 2; h++) {
                float mn = bc[wm * 64 + i * 16 + (lane >> 2) + h * 8];
                float e0 = __expf(acc[i][0][2*h]   + mk4[0][0] - mn);
                float e1 = __expf(acc[i][0][2*h+1] + mk4[0][1] - mn);
                float e2 = __expf(acc[i][1][2*h]   + mk4[1][0] - mn);
                float e3 = __expf(acc[i][1][2*h+1] + mk4[1][1] - mn);
                ls[i][h] = (e0 + e1) + (e2 + e3);
            }
        #pragma unroll
        for (int i = 0; i < 4; i++)
            #pragma unroll
            for (int h = 0; h < 2; h++) {
                ls[i][h] += __shfl_xor_sync(0xffffffffu, ls[i][h], 1);
                ls[i][h] += __shfl_xor_sync(0xffffffffu, ls[i][h], 2);
            }
        if ((lane & 3) == 0) {
            #pragma unroll
            for (int i = 0; i < 4; i++)
                #pragma unroll
                for (int h = 0; h < 2; h++)
                    tr[wn * 128 + wm * 64 + i * 16 + (lane >> 2) + h * 8] = ls[i][h];
        }
        __syncthreads();
        if (tid < 128)
            srow[tid] += (tr[tid] + tr[128 + tid]) + (tr[256 + tid] + tr[384 + tid]);
    }

    __syncthreads();
    if (tid < 128) srow[tid] = 1.0f / srow[tid];
    __syncthreads();

    // ================= PASS B: probs + PV =================
    float O[4][2][4] = {};
    issueKV(0);
    issueKV(1);
    for (int it = 0; it < 32; it++) {
        asm volatile("cp.async.wait_group 1;");
        __syncthreads();
        issueKV(it + 2);
        const int buf = it % 3;
        score(buf, acc);

        const int key0 = it * 64;
        float mk4[2][2];
        #pragma unroll
        for (int j = 0; j < 2; j++)
            #pragma unroll
            for (int c = 0; c < 2; c++)
                mk4[j][c] = MK[key0 + wn * 16 + j * 8 + ((lane & 3) << 1) + c] ? NEGV : 0.f;

        #pragma unroll
        for (int i = 0; i < 4; i++) {
            int r  = wm * 64 + i * 16 + (lane >> 2);
            int r8 = r + 8;
            float mn0 = mrow[r],  iv0 = srow[r];
            float mn1 = mrow[r8], iv1 = srow[r8];
            #pragma unroll
            for (int j = 0; j < 2; j++) {
                int keyloc = wn * 16 + j * 8 + ((lane & 3) << 1);
                float p0 = __expf(acc[i][j][0] + mk4[j][0] - mn0) * iv0;
                float p1 = __expf(acc[i][j][1] + mk4[j][1] - mn0) * iv0;
                float p2 = __expf(acc[i][j][2] + mk4[j][0] - mn1) * iv1;
                float p3 = __expf(acc[i][j][3] + mk4[j][1] - mn1) * iv1;
                *(float2*)&P[(size_t)(q0 + r)  * S + key0 + keyloc] = make_float2(p0, p1);
                *(float2*)&P[(size_t)(q0 + r8) * S + key0 + keyloc] = make_float2(p2, p3);
                int kqg = keyloc >> 2;
                int st = kqg >> 2, kq = kqg & 3, ic = keyloc & 3;
                *(float2*)&sP[st * 2048 + chidx(r,  kq) + ic] =
                    make_float2(to_tf32(p0), to_tf32(p1));
                *(float2*)&sP[st * 2048 + chidx(r8, kq) + ic] =
                    make_float2(to_tf32(p2), to_tf32(p3));
            }
        }
        __syncthreads();

        // PV: A = sP (128 x 64 keys), B = sV[buf] ([key][d] swizzled)
        const uint32_t pb = smb + (uint32_t)(34304 * 4);
        const float* sVb = sV + buf * 4608;
        #pragma unroll
        for (int st = 0; st < 4; st++) {
            #pragma unroll
            for (int ks = 0; ks < 2; ks++) {
                uint32_t a[4][4];
                uint32_t bfr[2][2];
                const int akq = ks * 2 + aKqOff;
                #pragma unroll
                for (int i = 0; i < 4; i++) {
                    uint32_t addr = pb + (uint32_t)((st * 2048 +
                                      chidx(aRowBase + i * 16, akq)) * 4);
                    ldsm4(a[i][0], a[i][1], a[i][2], a[i][3], addr);
                }
                int k0 = st * 16 + ks * 8 + (lane & 3);
                int k1 = k0 + 4;
                int w0 = ((k0 >> 2) & 3) << 3;
                int w1 = ((k1 >> 2) & 3) << 3;
                #pragma unroll
                for (int j = 0; j < 2; j++) {
                    int d = wn * 16 + j * 8 + (lane >> 2);
                    int ds = (d & ~3), dr = d & 3;
                    bfr[j][0] = __float_as_uint(sVb[k0 * 72 + (ds ^ w0) + dr]);
                    bfr[j][1] = __float_as_uint(sVb[k1 * 72 + (ds ^ w1) + dr]);
                }
                #pragma unroll
                for (int i = 0; i < 4; i++)
                    #pragma unroll
                    for (int j = 0; j < 2; j++)
                        mma8(O[i][j], a[i], bfr[j]);
            }
        }
        __syncthreads();
    }

    // ---- write O (rounded to tf32 for O-proj cp.async GEMM) ----
    #pragma unroll
    for (int i = 0; i < 4; i++) {
        int r0 = q0 + wm * 64 + i * 16 + (lane >> 2);
        #pragma unroll
        for (int j = 0; j < 2; j++) {
            int col = wn * 16 + j * 8 + ((lane & 3) << 1);
            *(float2*)&AO[(size_t)r0 * ld + col] =
                make_float2(to_tf32(O[i][j][0]), to_tf32(O[i][j][1]));
            *(float2*)&AO[(size_t)(r0 + 8) * ld + col] =
                make_float2(to_tf32(O[i][j][2]), to_tf32(O[i][j][3]));
        }
    }
}

// ---------------- pre-pass: round to tf32 (float4) ----------------
__global__ __launch_bounds__(256) void round_kernel(const float* __restrict__ in,
                                                    float* __restrict__ out, int n4)
{
    int i = blockIdx.x * 256 + threadIdx.x;
    if (i < n4) {
        float4 v = ((const float4*)in)[i];
        v.x = to_tf32(v.x); v.y = to_tf32(v.y);
        v.z = to_tf32(v.z); v.w = to_tf32(v.w);
        ((float4*)out)[i] = v;
    }
}

// ---------------- pre-pass: transpose + round ----------------
__global__ __launch_bounds__(256) void transpose_round(const float* __restrict__ in,
                                                       float* __restrict__ out,
                                                       int K, int N)
{
    __shared__ float tile[32][33];
    int n = blockIdx.x * 32 + threadIdx.x;
    int k = blockIdx.y * 32 + threadIdx.y;
    #pragma unroll
    for (int i = 0; i < 32; i += 8)
        tile[threadIdx.y + i][threadIdx.x] = in[(size_t)(k + i) * N + n];
    __syncthreads();
    int n2 = blockIdx.x * 32 + threadIdx.y;
    int k2 = blockIdx.y * 32 + threadIdx.x;
    #pragma unroll
    for (int i = 0; i < 32; i += 8)
        out[(size_t)(n2 + i) * K + k2] = to_tf32(tile[threadIdx.x][threadIdx.y + i]);
}

// ---------------- layernorm(resid + y) * g + beta ----------------
__global__ __launch_bounds__(256) void ln_kernel(
    const float* __restrict__ resid, const float* __restrict__ y,
    const float* __restrict__ g, const float* __restrict__ beta,
    float* __restrict__ out, float* __restrict__ out_r)
{
    const int row = blockIdx.x;
    const int tid = threadIdx.x;
    float4 a = ((const float4*)(resid + (size_t)row * D))[tid];
    float4 c = ((const float4*)(y + (size_t)row * D))[tid];
    float v0 = a.x + c.x, v1 = a.y + c.y, v2 = a.z + c.z, v3 = a.w + c.w;

    __shared__ float sh[256], sh2[256];
    sh[tid]  = v0 + v1 + v2 + v3;
    sh2[tid] = v0*v0 + v1*v1 + v2*v2 + v3*v3;
    __syncthreads();
    for (int st = 128; st > 0; st >>= 1) {
        if (tid < st) { sh[tid] += sh[tid + st]; sh2[tid] += sh2[tid + st]; }
        __syncthreads();
    }
    float mean = sh[0] * (1.0f / D);
    float var  = sh2[0] * (1.0f / D) - mean * mean;
    float rstd = rsqrtf(var + 1e-5f);

    float4 g4 = ((const float4*)g)[tid];
    float4 b4 = ((const float4*)beta)[tid];
    float4 o;
    o.x = (v0 - mean) * rstd * g4.x + b4.x;
    o.y = (v1 - mean) * rstd * g4.y + b4.y;
    o.z = (v2 - mean) * rstd * g4.z + b4.z;
    o.w = (v3 - mean) * rstd * g4.w + b4.w;
    ((float4*)(out + (size_t)row * D))[tid] = o;
    if (out_r) {
        float4 r;
        r.x = to_tf32(o.x); r.y = to_tf32(o.y);
        r.z = to_tf32(o.z); r.w = to_tf32(o.w);
        ((float4*)(out_r + (size_t)row * D))[tid] = r;
    }
}

// ---------------- launcher ----------------
extern "C" void kernel_launch(void* const* d_in, const int* in_sizes, int n_in,
                              void* d_out, int out_size)
{
    const float* x    = (const float*)d_in[0];
    const unsigned char* mask = (const unsigned char*)d_in[1];
    const float* Wq   = (const float*)d_in[2];
    const float* bq   = (const float*)d_in[3];
    const float* Wk   = (const float*)d_in[4];
    const float* bk   = (const float*)d_in[5];
    const float* Wv   = (const float*)d_in[6];
    const float* bv   = (const float*)d_in[7];
    const float* Wo   = (const float*)d_in[8];
    const float* bo   = (const float*)d_in[9];
    const float* ln1g = (const float*)d_in[10];
    const float* ln1b = (const float*)d_in[11];
    const float* W1   = (const float*)d_in[12];
    const float* b1   = (const float*)d_in[13];
    const float* W2   = (const float*)d_in[14];
    const float* b2   = (const float*)d_in[15];
    const float* ln2g = (const float*)d_in[16];
    const float* ln2b = (const float*)d_in[17];

    float *q, *k, *v, *ao, *x1, *x1r, *y, *h, *attn, *xr;
    float *wqt, *wkt, *wvt, *wot, *w1t, *w2t;
    cudaGetSymbolAddress((void**)&q,   g_q);
    cudaGetSymbolAddress((void**)&k,   g_k);
    cudaGetSymbolAddress((void**)&v,   g_v);
    cudaGetSymbolAddress((void**)&ao,  g_ao);
    cudaGetSymbolAddress((void**)&x1,  g_x1);
    cudaGetSymbolAddress((void**)&x1r, g_x1r);
    cudaGetSymbolAddress((void**)&y,   g_y);
    cudaGetSymbolAddress((void**)&h,   g_h);
    cudaGetSymbolAddress((void**)&attn, g_attn);
    cudaGetSymbolAddress((void**)&xr,  g_xr);
    cudaGetSymbolAddress((void**)&wqt, g_wqt);
    cudaGetSymbolAddress((void**)&wkt, g_wkt);
    cudaGetSymbolAddress((void**)&wvt, g_wvt);
    cudaGetSymbolAddress((void**)&wot, g_wot);
    cudaGetSymbolAddress((void**)&w1t, g_w1t);
    cudaGetSymbolAddress((void**)&w2t, g_w2t);

    const long long X  = (long long)T * D;
    const long long AW = (long long)BATCH * H * (long long)S * S;
    float* xout;
    float* attnout;
    if ((long long)out_size >= X + AW) {
        xout = (float*)d_out;
        attnout = (float*)d_out + X;
    } else if ((long long)out_size == AW) {
        attnout = (float*)d_out;
        xout = ao;
    } else {
        xout = (float*)d_out;
        attnout = attn;
    }

    static int af_attr_set = 0;
    if (!af_attr_set) {
        cudaFuncSetAttribute(attn_fused,
                             cudaFuncAttributeMaxDynamicSharedMemorySize, AF_SMEM_BYTES);
        af_attr_set = 1;
    }

    dim3 blk(256);
    dim3 tb(32, 8);
    const float scaling = 0.125f;

    // ---- pre-pass: round x; transpose+round weights ----
    round_kernel<<<dim3((T*D/4 + 255)/256), blk>>>(x, xr, T*D/4);
    transpose_round<<<dim3(D/32, D/32), tb>>>(Wq, wqt, D, D);
    transpose_round<<<dim3(D/32, D/32), tb>>>(Wk, wkt, D, D);
    transpose_round<<<dim3(D/32, D/32), tb>>>(Wv, wvt, D, D);
    transpose_round<<<dim3(D/32, D/32), tb>>>(Wo, wot, D, D);
    transpose_round<<<dim3(FFN_DIM/32, D/32), tb>>>(W1, w1t, D, FFN_DIM);
    transpose_round<<<dim3(D/32, FFN_DIM/32), tb>>>(W2, w2t, FFN_DIM, D);

    // ---- QKV projections (cp.async, rounded outputs) ----
    mma_gemm_ca<1,0,true><<<dim3(D/128, T/128), blk>>>(xr, D, wqt, D, bq, q, D, D, scaling);
    mma_gemm_ca<0,0,true><<<dim3(D/128, T/128), blk>>>(xr, D, wkt, D, bk, k, D, D, 1.0f);
    mma_gemm_ca<0,0,true><<<dim3(D/128, T/128), blk>>>(xr, D, wvt, D, bv, v, D, D, 1.0f);

    // ---- fused attention: QK^T + mask + softmax + PV ----
    attn_fused<<<dim3(S/128, BATCH*H), blk, AF_SMEM_BYTES>>>(q, k, v, mask, attnout, ao);

    // ---- O-proj + LN1 ----
    mma_gemm_ca<0,0,false><<<dim3(D/128, T/128), blk>>>(ao, D, wot, D, bo, y, D, D, 1.0f);
    ln_kernel<<<dim3(T), blk>>>(x, y, ln1g, ln1b, x1, x1r);

    // ---- FFN + LN2 ----
    mma_gemm_ca<2,0,true><<<dim3(FFN_DIM/128, T/128), blk>>>(x1r, D, w1t, D, b1, h, FFN_DIM, D, 1.0f);
    mma_gemm_ca<0,0,false><<<dim3(D/128, T/128), blk>>>(h, FFN_DIM, w2t, FFN_DIM, b2, y, D, FFN_DIM, 1.0f);
    ln_kernel<<<dim3(T), blk>>>(x1, y, ln2g, ln2b, xout, nullptr);
}

// round 8
// speedup vs baseline: 1.0292x; 1.0292x over previous
#include <cuda_runtime.h>
#include <math.h>
#include <stdint.h>

#define S 2048
#define BATCH 2
#define D 1024
#define H 16
#define FFN_DIM 4096
#define T (S*BATCH)
#define NEGV -1e9f

// ---------------- scratch (device globals; no allocation allowed) ----------------
__device__ float g_q[(size_t)T*D];
__device__ float g_k[(size_t)T*D];
__device__ float g_v[(size_t)T*D];
__device__ float g_ao[(size_t)T*D];
__device__ float g_x1[(size_t)T*D];
__device__ float g_x1r[(size_t)T*D];
__device__ float g_y[(size_t)T*D];
__device__ float g_h[(size_t)T*FFN_DIM];
__device__ float g_attn[(size_t)BATCH*H*S*S];   // fallback probs target only
__device__ float g_xr[(size_t)T*D];
__device__ float g_wqt[(size_t)D*D];
__device__ float g_wkt[(size_t)D*D];
__device__ float g_wvt[(size_t)D*D];
__device__ float g_wot[(size_t)D*D];
__device__ float g_w1t[(size_t)D*FFN_DIM];
__device__ float g_w2t[(size_t)D*FFN_DIM];

// ---------------- helpers ----------------
__device__ __forceinline__ float to_tf32(float x) {
    uint32_t u;
    asm("cvt.rna.tf32.f32 %0, %1;" : "=r"(u) : "f"(x));
    return __uint_as_float(u);
}

__device__ __forceinline__ void mma8(float* c, const uint32_t* a, const uint32_t* b) {
    asm("mma.sync.aligned.m16n8k8.row.col.f32.tf32.tf32.f32 "
        "{%0,%1,%2,%3},{%4,%5,%6,%7},{%8,%9},{%0,%1,%2,%3};"
        : "+f"(c[0]), "+f"(c[1]), "+f"(c[2]), "+f"(c[3])
        : "r"(a[0]), "r"(a[1]), "r"(a[2]), "r"(a[3]),
          "r"(b[0]), "r"(b[1]));
}

__device__ __forceinline__ void ldsm4(uint32_t& r0, uint32_t& r1, uint32_t& r2, uint32_t& r3,
                                      uint32_t addr) {
    asm volatile("ldmatrix.sync.aligned.m8n8.x4.shared.b16 {%0,%1,%2,%3}, [%4];"
                 : "=r"(r0), "=r"(r1), "=r"(r2), "=r"(r3) : "r"(addr));
}

__device__ __forceinline__ void cpasync16(uint32_t dst, const float* src) {
    asm volatile("cp.async.cg.shared.global [%0], [%1], 16;" :: "r"(dst), "l"(src));
}

__device__ __forceinline__ int chidx(int row, int kq) {
    return (row * 4 + (kq ^ ((row >> 1) & 3))) * 4;
}

__device__ __forceinline__ float gelu(float v) {
    return 0.5f * v * (1.0f + erff(v * 0.70710678118654752f));
}

// =====================================================================
// cp.async 3-stage tf32 GEMM (round-5, unchanged).
// =====================================================================
template<int EPI, int ZMODE, bool ROUND>
__global__ __launch_bounds__(256, 2) void mma_gemm_ca(
    const float* __restrict__ A, long long lda,
    const float* __restrict__ Bg, long long ldb,
    const float* __restrict__ bias,
    float* __restrict__ C, long long ldc,
    int K, float scale)
{
    constexpr int MT = 4, NT = 4, STG = 3;

    __shared__ float sA[STG][2048];
    __shared__ float sB[STG][2048];

    const int tid  = threadIdx.x;
    const int lane = tid & 31;
    const int w    = tid >> 5;
    const int wm   = w & 1;
    const int wn   = w >> 1;
    const int m0   = blockIdx.y * 128;
    const int n0   = blockIdx.x * 128;
    const int z    = blockIdx.z;

    if (ZMODE == 1) {
        int hoff = (z >> 4) * D + (z & 15) * 64;
        A  += hoff;
        Bg += hoff;
        C  += (size_t)z * S * S;
    }

    float acc[MT][NT][4] = {};
    const int ntiles = K >> 4;

    const int fm = lane >> 3;
    const int fj = lane & 7;
    const int aRowBase = wm * 64 + (fm & 1) * 8 + fj;
    const int aKqOff   = fm >> 1;
    const int bTileOff = fm >> 1;
    const int bKqOff   = fm & 1;

    const uint32_t sA0 = (uint32_t)__cvta_generic_to_shared(&sA[0][0]);
    const uint32_t sB0 = (uint32_t)__cvta_generic_to_shared(&sB[0][0]);

    const int sRow0 = tid >> 2,  sKq = tid & 3;
    const int sRow1 = sRow0 + 64;

    auto issue = [&](int t) {
        if (t < ntiles) {
            const int buf = t % STG;
            const int k0  = t << 4;
            const uint32_t aBase = sA0 + buf * 8192;
            const uint32_t bBase = sB0 + buf * 8192;
            cpasync16(aBase + (uint32_t)(chidx(sRow0, sKq) * 4),
                      A + (size_t)(m0 + sRow0) * lda + k0 + sKq * 4);
            cpasync16(aBase + (uint32_t)(chidx(sRow1, sKq) * 4),
                      A + (size_t)(m0 + sRow1) * lda + k0 + sKq * 4);
            cpasync16(bBase + (uint32_t)(chidx(sRow0, sKq) * 4),
                      Bg + (size_t)(n0 + sRow0) * ldb + k0 + sKq * 4);
            cpasync16(bBase + (uint32_t)(chidx(sRow1, sKq) * 4),
                      Bg + (size_t)(n0 + sRow1) * ldb + k0 + sKq * 4);
        }
        asm volatile("cp.async.commit_group;");
    };

    auto compute = [&](int buf) {
        const uint32_t aBase = sA0 + buf * 8192;
        const uint32_t bBase = sB0 + buf * 8192;
        #pragma unroll
        for (int ks = 0; ks < 2; ks++) {
            uint32_t a[MT][4];
            uint32_t b[NT][2];
            const int akq = ks * 2 + aKqOff;
            const int bkq = ks * 2 + bKqOff;
            #pragma unroll
            for (int i = 0; i < MT; i++) {
                uint32_t addr = aBase + (uint32_t)(chidx(aRowBase + i * 16, akq) * 4);
                ldsm4(a[i][0], a[i][1], a[i][2], a[i][3], addr);
            }
            #pragma unroll
            for (int j2 = 0; j2 < NT; j2 += 2) {
                int tile = wn * NT + j2 + bTileOff;
                uint32_t addr = bBase + (uint32_t)(chidx(tile * 8 + fj, bkq) * 4);
                ldsm4(b[j2][0], b[j2][1], b[j2 + 1][0], b[j2 + 1][1], addr);
            }
            #pragma unroll
            for (int i = 0; i < MT; i++)
                #pragma unroll
                for (int j = 0; j < NT; j++)
                    mma8(acc[i][j], a[i], b[j]);
        }
    };

    issue(0);
    issue(1);
    for (int t = 0; t < ntiles; t++) {
        asm volatile("cp.async.wait_group 1;");
        __syncthreads();
        issue(t + 2);
        compute(t % STG);
    }

    #pragma unroll
    for (int i = 0; i < MT; i++) {
        int r0 = m0 + wm * 64 + i * 16 + (lane >> 2);
        #pragma unroll
        for (int j = 0; j < NT; j++) {
            int col = n0 + wn * 32 + j * 8 + ((lane & 3) << 1);
            float bx = 0.f, by = 0.f;
            if (EPI != 3) {
                float2 bb = *(const float2*)&bias[col];
                bx = bb.x; by = bb.y;
            }
            float v0 = acc[i][j][0] + bx, v1 = acc[i][j][1] + by;
            float v2 = acc[i][j][2] + bx, v3 = acc[i][j][3] + by;
            if (EPI == 1) { v0 *= scale; v1 *= scale; v2 *= scale; v3 *= scale; }
            if (EPI == 2) { v0 = gelu(v0); v1 = gelu(v1); v2 = gelu(v2); v3 = gelu(v3); }
            if (ROUND) {
                v0 = to_tf32(v0); v1 = to_tf32(v1);
                v2 = to_tf32(v2); v3 = to_tf32(v3);
            }
            *(float2*)&C[(size_t)r0 * ldc + col]       = make_float2(v0, v1);
            *(float2*)&C[(size_t)(r0 + 8) * ldc + col] = make_float2(v2, v3);
        }
    }
}

// =====================================================================
// Fused attention v2: per-warp row ownership for stats (no stat barriers).
// Each warp owns 16 q-rows x all 64 keys for score/softmax; PV uses the
// round-7 (2m x 4n) layout reading sP across warps behind one barrier.
// float offsets: sQ 0 (8192) | sK 8192 (3x4096) | sV 20480 (3x4608)
//                sP 34304 (8192) | fmask 42496 (2048)
// =====================================================================
#define AF_SMEM_FLOATS 44544
#define AF_SMEM_BYTES (AF_SMEM_FLOATS * 4)

__global__ __launch_bounds__(256, 1) void attn_fused(
    const float* __restrict__ qg, const float* __restrict__ kg,
    const float* __restrict__ vg, const unsigned char* __restrict__ mask,
    float* __restrict__ probs, float* __restrict__ aog)
{
    extern __shared__ float sm[];
    const int tid  = threadIdx.x;
    const int lane = tid & 31;
    const int w    = tid >> 5;
    const int wm   = w & 1;
    const int wn   = w >> 1;
    const int q0   = blockIdx.x * 128;
    const int z    = blockIdx.y;
    const int b    = z >> 4, hh = z & 15;
    const long long ld = (long long)BATCH * D;

    const float* Q = qg + (size_t)b * D + hh * 64;
    const float* K = kg + (size_t)b * D + hh * 64;
    const float* V = vg + (size_t)b * D + hh * 64;
    float* P  = probs + (size_t)z * S * S;
    float* AO = aog + (size_t)b * D + hh * 64;
    const unsigned char* MK = mask + (size_t)b * S;

    const uint32_t smb = (uint32_t)__cvta_generic_to_shared(sm);
    float* sV    = sm + 20480;
    float* sP    = sm + 34304;
    float* fmask = sm + 42496;

    const int fm = lane >> 3;
    const int fj = lane & 7;
    // new (per-warp-band) geometry for scores
    const int aRowN = w * 16 + (fm & 1) * 8 + fj;
    // old geometry for PV
    const int aRowBase = wm * 64 + (fm & 1) * 8 + fj;
    const int aKqOff   = fm >> 1;
    const int bKqOff   = fm & 1;

    // ---- mask -> smem float table ----
    #pragma unroll
    for (int u = 0; u < 8; u++) {
        int i = tid + u * 256;
        fmask[i] = MK[i] ? NEGV : 0.0f;
    }

    // ---- stage Q once (folded into first K commit group) ----
    #pragma unroll
    for (int u = 0; u < 8; u++) {
        int c = tid + u * 256;
        int row = c >> 4, kqg = c & 15;
        cpasync16(smb + (uint32_t)(((kqg >> 2) * 2048 + chidx(row, kqg & 3)) * 4),
                  Q + (size_t)(q0 + row) * ld + kqg * 4);
    }

    auto issueK = [&](int it) {
        if (it < 32) {
            const int buf = it % 3;
            const int key0 = it * 64;
            const uint32_t kb = smb + (uint32_t)((8192 + buf * 4096) * 4);
            #pragma unroll
            for (int u = 0; u < 4; u++) {
                int c = tid + u * 256;
                int key = c >> 4, kqg = c & 15;
                cpasync16(kb + (uint32_t)(((kqg >> 2) * 1024 + chidx(key, kqg & 3)) * 4),
                          K + (size_t)(key0 + key) * ld + kqg * 4);
            }
        }
        asm volatile("cp.async.commit_group;");
    };
    auto issueKV = [&](int it) {
        if (it < 32) {
            const int buf = it % 3;
            const int key0 = it * 64;
            const uint32_t kb = smb + (uint32_t)((8192 + buf * 4096) * 4);
            const uint32_t vb = smb + (uint32_t)((20480 + buf * 4608) * 4);
            #pragma unroll
            for (int u = 0; u < 4; u++) {
                int c = tid + u * 256;
                int key = c >> 4, kqg = c & 15;
                cpasync16(kb + (uint32_t)(((kqg >> 2) * 1024 + chidx(key, kqg & 3)) * 4),
                          K + (size_t)(key0 + key) * ld + kqg * 4);
            }
            #pragma unroll
            for (int u = 0; u < 4; u++) {
                int c = tid + u * 256;
                int key = c >> 4, dg = c & 15;
                int wk = ((key >> 2) & 3) << 3;
                cpasync16(vb + (uint32_t)((key * 72 + ((dg * 4) ^ wk)) * 4),
                          V + (size_t)(key0 + key) * ld + dg * 4);
            }
        }
        asm volatile("cp.async.commit_group;");
    };

    // scores, warp-band layout: acc[j][c] = (row w*16+(lane>>2)+{0,8}, key j*8+(lane&3)*2+{0,1})
    auto score_n = [&](int buf, float (&acc)[8][4]) {
        #pragma unroll
        for (int j = 0; j < 8; j++)
            #pragma unroll
            for (int c = 0; c < 4; c++) acc[j][c] = 0.f;
        const uint32_t kb = smb + (uint32_t)((8192 + buf * 4096) * 4);
        #pragma unroll
        for (int st = 0; st < 4; st++) {
            #pragma unroll
            for (int ks = 0; ks < 2; ks++) {
                uint32_t a[4];
                uint32_t bfr[8][2];
                const int akq = ks * 2 + aKqOff;
                const int bkq = ks * 2 + bKqOff;
                {
                    uint32_t addr = smb + (uint32_t)((st * 2048 + chidx(aRowN, akq)) * 4);
                    ldsm4(a[0], a[1], a[2], a[3], addr);
                }
                #pragma unroll
                for (int j2 = 0; j2 < 8; j2 += 2) {
                    int tile = j2 + (fm >> 1);
                    uint32_t addr = kb + (uint32_t)((st * 1024 + chidx(tile * 8 + fj, bkq)) * 4);
                    ldsm4(bfr[j2][0], bfr[j2][1], bfr[j2 + 1][0], bfr[j2 + 1][1], addr);
                }
                #pragma unroll
                for (int j = 0; j < 8; j++)
                    mma8(acc[j], a, bfr[j]);
            }
        }
    };

    float acc[8][4];
    float m0 = -1e30f, m1 = -1e30f, s0 = 0.f, s1 = 0.f;

    // ================= PASS A: row stats (register-resident) =================
    issueK(0);
    issueK(1);
    for (int it = 0; it < 32; it++) {
        asm volatile("cp.async.wait_group 1;");
        __syncthreads();
        issueK(it + 2);
        score_n(it % 3, acc);

        float2 fmj[8];
        #pragma unroll
        for (int j = 0; j < 8; j++)
            fmj[j] = *(const float2*)&fmask[it * 64 + j * 8 + ((lane & 3) << 1)];

        float mt0 = -1e30f, mt1 = -1e30f;
        #pragma unroll
        for (int j = 0; j < 8; j++) {
            mt0 = fmaxf(mt0, fmaxf(acc[j][0] + fmj[j].x, acc[j][1] + fmj[j].y));
            mt1 = fmaxf(mt1, fmaxf(acc[j][2] + fmj[j].x, acc[j][3] + fmj[j].y));
        }
        mt0 = fmaxf(mt0, __shfl_xor_sync(0xffffffffu, mt0, 1));
        mt0 = fmaxf(mt0, __shfl_xor_sync(0xffffffffu, mt0, 2));
        mt1 = fmaxf(mt1, __shfl_xor_sync(0xffffffffu, mt1, 1));
        mt1 = fmaxf(mt1, __shfl_xor_sync(0xffffffffu, mt1, 2));

        float mn0 = fmaxf(m0, mt0), mn1 = fmaxf(m1, mt1);
        float c0 = __expf(m0 - mn0), c1 = __expf(m1 - mn1);
        float ls0 = 0.f, ls1 = 0.f;
        #pragma unroll
        for (int j = 0; j < 8; j++) {
            ls0 += __expf(acc[j][0] + fmj[j].x - mn0) + __expf(acc[j][1] + fmj[j].y - mn0);
            ls1 += __expf(acc[j][2] + fmj[j].x - mn1) + __expf(acc[j][3] + fmj[j].y - mn1);
        }
        ls0 += __shfl_xor_sync(0xffffffffu, ls0, 1);
        ls0 += __shfl_xor_sync(0xffffffffu, ls0, 2);
        ls1 += __shfl_xor_sync(0xffffffffu, ls1, 1);
        ls1 += __shfl_xor_sync(0xffffffffu, ls1, 2);

        s0 = s0 * c0 + ls0;
        s1 = s1 * c1 + ls1;
        m0 = mn0; m1 = mn1;
    }

    const float inv0 = 1.0f / s0;
    const float inv1 = 1.0f / s1;

    // ================= PASS B: probs + PV =================
    float O[4][2][4] = {};
    issueKV(0);
    issueKV(1);
    for (int it = 0; it < 32; it++) {
        asm volatile("cp.async.wait_group 1;");
        __syncthreads();
        issueKV(it + 2);
        const int buf = it % 3;
        score_n(buf, acc);

        const int key0 = it * 64;
        const int r0l = w * 16 + (lane >> 2);
        const int r1l = r0l + 8;
        #pragma unroll
        for (int j = 0; j < 8; j++) {
            float2 fmv = *(const float2*)&fmask[key0 + j * 8 + ((lane & 3) << 1)];
            float p0 = __expf(acc[j][0] + fmv.x - m0) * inv0;
            float p1 = __expf(acc[j][1] + fmv.y - m0) * inv0;
            float p2 = __expf(acc[j][2] + fmv.x - m1) * inv1;
            float p3 = __expf(acc[j][3] + fmv.y - m1) * inv1;
            int keyloc = j * 8 + ((lane & 3) << 1);
            *(float2*)&P[(size_t)(q0 + r0l) * S + key0 + keyloc] = make_float2(p0, p1);
            *(float2*)&P[(size_t)(q0 + r1l) * S + key0 + keyloc] = make_float2(p2, p3);
            int kqg = keyloc >> 2;
            int st = kqg >> 2, kq = kqg & 3, ic = keyloc & 3;
            *(float2*)&sP[st * 2048 + chidx(r0l, kq) + ic] =
                make_float2(to_tf32(p0), to_tf32(p1));
            *(float2*)&sP[st * 2048 + chidx(r1l, kq) + ic] =
                make_float2(to_tf32(p2), to_tf32(p3));
        }
        __syncthreads();

        // PV (round-7 layout): A = sP (128 x 64 keys), B = sV[buf]
        const uint32_t pb = smb + (uint32_t)(34304 * 4);
        const float* sVb = sV + buf * 4608;
        #pragma unroll
        for (int st = 0; st < 4; st++) {
            #pragma unroll
            for (int ks = 0; ks < 2; ks++) {
                uint32_t a[4][4];
                uint32_t bfr[2][2];
                const int akq = ks * 2 + aKqOff;
                #pragma unroll
                for (int i = 0; i < 4; i++) {
                    uint32_t addr = pb + (uint32_t)((st * 2048 +
                                      chidx(aRowBase + i * 16, akq)) * 4);
                    ldsm4(a[i][0], a[i][1], a[i][2], a[i][3], addr);
                }
                int k0 = st * 16 + ks * 8 + (lane & 3);
                int k1 = k0 + 4;
                int w0 = ((k0 >> 2) & 3) << 3;
                int w1 = ((k1 >> 2) & 3) << 3;
                #pragma unroll
                for (int j = 0; j < 2; j++) {
                    int d = wn * 16 + j * 8 + (lane >> 2);
                    int ds = (d & ~3), dr = d & 3;
                    bfr[j][0] = __float_as_uint(sVb[k0 * 72 + (ds ^ w0) + dr]);
                    bfr[j][1] = __float_as_uint(sVb[k1 * 72 + (ds ^ w1) + dr]);
                }
                #pragma unroll
                for (int i = 0; i < 4; i++)
                    #pragma unroll
                    for (int j = 0; j < 2; j++)
                        mma8(O[i][j], a[i], bfr[j]);
            }
        }
        __syncthreads();
    }

    // ---- write O (rounded to tf32 for O-proj cp.async GEMM) ----
    #pragma unroll
    for (int i = 0; i < 4; i++) {
        int r0 = q0 + wm * 64 + i * 16 + (lane >> 2);
        #pragma unroll
        for (int j = 0; j < 2; j++) {
            int col = wn * 16 + j * 8 + ((lane & 3) << 1);
            *(float2*)&AO[(size_t)r0 * ld + col] =
                make_float2(to_tf32(O[i][j][0]), to_tf32(O[i][j][1]));
            *(float2*)&AO[(size_t)(r0 + 8) * ld + col] =
                make_float2(to_tf32(O[i][j][2]), to_tf32(O[i][j][3]));
        }
    }
}

// ---------------- pre-pass: round to tf32 (float4) ----------------
__global__ __launch_bounds__(256) void round_kernel(const float* __restrict__ in,
                                                    float* __restrict__ out, int n4)
{
    int i = blockIdx.x * 256 + threadIdx.x;
    if (i < n4) {
        float4 v = ((const float4*)in)[i];
        v.x = to_tf32(v.x); v.y = to_tf32(v.y);
        v.z = to_tf32(v.z); v.w = to_tf32(v.w);
        ((float4*)out)[i] = v;
    }
}

// ---------------- pre-pass: transpose + round ----------------
__global__ __launch_bounds__(256) void transpose_round(const float* __restrict__ in,
                                                       float* __restrict__ out,
                                                       int K, int N)
{
    __shared__ float tile[32][33];
    int n = blockIdx.x * 32 + threadIdx.x;
    int k = blockIdx.y * 32 + threadIdx.y;
    #pragma unroll
    for (int i = 0; i < 32; i += 8)
        tile[threadIdx.y + i][threadIdx.x] = in[(size_t)(k + i) * N + n];
    __syncthreads();
    int n2 = blockIdx.x * 32 + threadIdx.y;
    int k2 = blockIdx.y * 32 + threadIdx.x;
    #pragma unroll
    for (int i = 0; i < 32; i += 8)
        out[(size_t)(n2 + i) * K + k2] = to_tf32(tile[threadIdx.x][threadIdx.y + i]);
}

// ---------------- layernorm(resid + y) * g + beta ----------------
__global__ __launch_bounds__(256) void ln_kernel(
    const float* __restrict__ resid, const float* __restrict__ y,
    const float* __restrict__ g, const float* __restrict__ beta,
    float* __restrict__ out, float* __restrict__ out_r)
{
    const int row = blockIdx.x;
    const int tid = threadIdx.x;
    float4 a = ((const float4*)(resid + (size_t)row * D))[tid];
    float4 c = ((const float4*)(y + (size_t)row * D))[tid];
    float v0 = a.x + c.x, v1 = a.y + c.y, v2 = a.z + c.z, v3 = a.w + c.w;

    __shared__ float sh[256], sh2[256];
    sh[tid]  = v0 + v1 + v2 + v3;
    sh2[tid] = v0*v0 + v1*v1 + v2*v2 + v3*v3;
    __syncthreads();
    for (int st = 128; st > 0; st >>= 1) {
        if (tid < st) { sh[tid] += sh[tid + st]; sh2[tid] += sh2[tid + st]; }
        __syncthreads();
    }
    float mean = sh[0] * (1.0f / D);
    float var  = sh2[0] * (1.0f / D) - mean * mean;
    float rstd = rsqrtf(var + 1e-5f);

    float4 g4 = ((const float4*)g)[tid];
    float4 b4 = ((const float4*)beta)[tid];
    float4 o;
    o.x = (v0 - mean) * rstd * g4.x + b4.x;
    o.y = (v1 - mean) * rstd * g4.y + b4.y;
    o.z = (v2 - mean) * rstd * g4.z + b4.z;
    o.w = (v3 - mean) * rstd * g4.w + b4.w;
    ((float4*)(out + (size_t)row * D))[tid] = o;
    if (out_r) {
        float4 r;
        r.x = to_tf32(o.x); r.y = to_tf32(o.y);
        r.z = to_tf32(o.z); r.w = to_tf32(o.w);
        ((float4*)(out_r + (size_t)row * D))[tid] = r;
    }
}

// ---------------- launcher ----------------
extern "C" void kernel_launch(void* const* d_in, const int* in_sizes, int n_in,
                              void* d_out, int out_size)
{
    const float* x    = (const float*)d_in[0];
    const unsigned char* mask = (const unsigned char*)d_in[1];
    const float* Wq   = (const float*)d_in[2];
    const float* bq   = (const float*)d_in[3];
    const float* Wk   = (const float*)d_in[4];
    const float* bk   = (const float*)d_in[5];
    const float* Wv   = (const float*)d_in[6];
    const float* bv   = (const float*)d_in[7];
    const float* Wo   = (const float*)d_in[8];
    const float* bo   = (const float*)d_in[9];
    const float* ln1g = (const float*)d_in[10];
    const float* ln1b = (const float*)d_in[11];
    const float* W1   = (const float*)d_in[12];
    const float* b1   = (const float*)d_in[13];
    const float* W2   = (const float*)d_in[14];
    const float* b2   = (const float*)d_in[15];
    const float* ln2g = (const float*)d_in[16];
    const float* ln2b = (const float*)d_in[17];

    float *q, *k, *v, *ao, *x1, *x1r, *y, *h, *attn, *xr;
    float *wqt, *wkt, *wvt, *wot, *w1t, *w2t;
    cudaGetSymbolAddress((void**)&q,   g_q);
    cudaGetSymbolAddress((void**)&k,   g_k);
    cudaGetSymbolAddress((void**)&v,   g_v);
    cudaGetSymbolAddress((void**)&ao,  g_ao);
    cudaGetSymbolAddress((void**)&x1,  g_x1);
    cudaGetSymbolAddress((void**)&x1r, g_x1r);
    cudaGetSymbolAddress((void**)&y,   g_y);
    cudaGetSymbolAddress((void**)&h,   g_h);
    cudaGetSymbolAddress((void**)&attn, g_attn);
    cudaGetSymbolAddress((void**)&xr,  g_xr);
    cudaGetSymbolAddress((void**)&wqt, g_wqt);
    cudaGetSymbolAddress((void**)&wkt, g_wkt);
    cudaGetSymbolAddress((void**)&wvt, g_wvt);
    cudaGetSymbolAddress((void**)&wot, g_wot);
    cudaGetSymbolAddress((void**)&w1t, g_w1t);
    cudaGetSymbolAddress((void**)&w2t, g_w2t);

    const long long X  = (long long)T * D;
    const long long AW = (long long)BATCH * H * (long long)S * S;
    float* xout;
    float* attnout;
    if ((long long)out_size >= X + AW) {
        xout = (float*)d_out;
        attnout = (float*)d_out + X;
    } else if ((long long)out_size == AW) {
        attnout = (float*)d_out;
        xout = ao;
    } else {
        xout = (float*)d_out;
        attnout = attn;
    }

    static int af_attr_set = 0;
    if (!af_attr_set) {
        cudaFuncSetAttribute(attn_fused,
                             cudaFuncAttributeMaxDynamicSharedMemorySize, AF_SMEM_BYTES);
        af_attr_set = 1;
    }

    dim3 blk(256);
    dim3 tb(32, 8);
    const float scaling = 0.125f;

    // ---- pre-pass: round x; transpose+round weights ----
    round_kernel<<<dim3((T*D/4 + 255)/256), blk>>>(x, xr, T*D/4);
    transpose_round<<<dim3(D/32, D/32), tb>>>(Wq, wqt, D, D);
    transpose_round<<<dim3(D/32, D/32), tb>>>(Wk, wkt, D, D);
    transpose_round<<<dim3(D/32, D/32), tb>>>(Wv, wvt, D, D);
    transpose_round<<<dim3(D/32, D/32), tb>>>(Wo, wot, D, D);
    transpose_round<<<dim3(FFN_DIM/32, D/32), tb>>>(W1, w1t, D, FFN_DIM);
    transpose_round<<<dim3(D/32, FFN_DIM/32), tb>>>(W2, w2t, FFN_DIM, D);

    // ---- QKV projections (cp.async, rounded outputs) ----
    mma_gemm_ca<1,0,true><<<dim3(D/128, T/128), blk>>>(xr, D, wqt, D, bq, q, D, D, scaling);
    mma_gemm_ca<0,0,true><<<dim3(D/128, T/128), blk>>>(xr, D, wkt, D, bk, k, D, D, 1.0f);
    mma_gemm_ca<0,0,true><<<dim3(D/128, T/128), blk>>>(xr, D, wvt, D, bv, v, D, D, 1.0f);

    // ---- fused attention: QK^T + mask + softmax + PV ----
    attn_fused<<<dim3(S/128, BATCH*H), blk, AF_SMEM_BYTES>>>(q, k, v, mask, attnout, ao);

    // ---- O-proj + LN1 ----
    mma_gemm_ca<0,0,false><<<dim3(D/128, T/128), blk>>>(ao, D, wot, D, bo, y, D, D, 1.0f);
    ln_kernel<<<dim3(T), blk>>>(x, y, ln1g, ln1b, x1, x1r);

    // ---- FFN + LN2 ----
    mma_gemm_ca<2,0,true><<<dim3(FFN_DIM/128, T/128), blk>>>(x1r, D, w1t, D, b1, h, FFN_DIM, D, 1.0f);
    mma_gemm_ca<0,0,false><<<dim3(D/128, T/128), blk>>>(h, FFN_DIM, w2t, FFN_DIM, b2, y, D, FFN_DIM, 1.0f);
    ln_kernel<<<dim3(T), blk>>>(x1, y, ln2g, ln2b, xout, nullptr);
}

// round 9
// speedup vs baseline: 1.7543x; 1.7045x over previous
#include <cuda_runtime.h>
#include <cuda_fp16.h>
#include <math.h>
#include <stdint.h>

#define S 2048
#define BATCH 2
#define D 1024
#define H 16
#define FFN_DIM 4096
#define T (S*BATCH)
#define NEGV -1e9f

// ---------------- scratch (device globals; no allocation allowed) ----------------
__device__ __half g_q[(size_t)T*D];
__device__ __half g_k[(size_t)T*D];
__device__ __half g_v[(size_t)T*D];
__device__ __half g_ao[(size_t)T*D];
__device__ float  g_x1[(size_t)T*D];
__device__ __half g_x1r[(size_t)T*D];
__device__ float  g_y[(size_t)T*D];
__device__ __half g_h[(size_t)T*FFN_DIM];
__device__ float  g_attn[(size_t)BATCH*H*S*S];   // fallback buffers only
__device__ __half g_xr[(size_t)T*D];
__device__ __half g_wqt[(size_t)D*D];
__device__ __half g_wkt[(size_t)D*D];
__device__ __half g_wvt[(size_t)D*D];
__device__ __half g_wot[(size_t)D*D];
__device__ __half g_w1t[(size_t)D*FFN_DIM];
__device__ __half g_w2t[(size_t)D*FFN_DIM];

// ---------------- helpers ----------------
__device__ __forceinline__ void mma16(float* c, const uint32_t* a, const uint32_t* b) {
    asm("mma.sync.aligned.m16n8k16.row.col.f32.f16.f16.f32 "
        "{%0,%1,%2,%3},{%4,%5,%6,%7},{%8,%9},{%0,%1,%2,%3};"
        : "+f"(c[0]), "+f"(c[1]), "+f"(c[2]), "+f"(c[3])
        : "r"(a[0]), "r"(a[1]), "r"(a[2]), "r"(a[3]),
          "r"(b[0]), "r"(b[1]));
}

__device__ __forceinline__ void ldsm4(uint32_t& r0, uint32_t& r1, uint32_t& r2, uint32_t& r3,
                                      uint32_t addr) {
    asm volatile("ldmatrix.sync.aligned.m8n8.x4.shared.b16 {%0,%1,%2,%3}, [%4];"
                 : "=r"(r0), "=r"(r1), "=r"(r2), "=r"(r3) : "r"(addr));
}

__device__ __forceinline__ void ldsm4t(uint32_t& r0, uint32_t& r1, uint32_t& r2, uint32_t& r3,
                                       uint32_t addr) {
    asm volatile("ldmatrix.sync.aligned.m8n8.x4.trans.shared.b16 {%0,%1,%2,%3}, [%4];"
                 : "=r"(r0), "=r"(r1), "=r"(r2), "=r"(r3) : "r"(addr));
}

__device__ __forceinline__ void cpasync16(uint32_t dst, const void* src) {
    asm volatile("cp.async.cg.shared.global [%0], [%1], 16;" :: "r"(dst), "l"(src));
}

// 16B-chunk indices (conflict-free for 16B staging phases and ldmatrix 8-row phases)
__device__ __forceinline__ int ch16(int row, int kq) {        // 4 chunks/row (GEMM, BK=32 halfs)
    return row * 4 + (kq ^ ((row >> 1) & 3));
}
__device__ __forceinline__ int ch8(int r, int q) {            // 8 chunks/row (attention, 64 halfs/row)
    return r * 8 + (q ^ (r & 7));
}

__device__ __forceinline__ float gelu(float v) {
    return 0.5f * v * (1.0f + erff(v * 0.70710678118654752f));
}

// =====================================================================
// fp16 cp.async 3-stage GEMM: C[M,N] = A[M,K]@B^T + bias (B given [N][K]).
// BM=128, BN=128, BK=32 halfs, 256 threads (8 warps, 2m x 4n).
// EPI: 0=bias, 1=bias*scale, 2=gelu(bias).  OUTH: write __half else float.
// =====================================================================
template<int EPI, bool OUTH>
__global__ __launch_bounds__(256, 2) void hgemm(
    const __half* __restrict__ A, long long lda,
    const __half* __restrict__ Bg, long long ldb,
    const float* __restrict__ bias,
    void* __restrict__ Cv, long long ldc,
    int K, float scale)
{
    constexpr int STG = 3;
    __shared__ __half sA[STG][128 * 32];
    __shared__ __half sB[STG][128 * 32];

    const int tid  = threadIdx.x;
    const int lane = tid & 31;
    const int w    = tid >> 5;
    const int wm   = w & 1;
    const int wn   = w >> 1;
    const int m0   = blockIdx.y * 128;
    const int n0   = blockIdx.x * 128;

    float acc[4][4][4] = {};
    const int ntiles = K >> 5;

    const int fm = lane >> 3;
    const int fj = lane & 7;
    const int aRowBase = wm * 64 + (fm & 1) * 8 + fj;
    const int aKqOff   = fm >> 1;
    const int bTileOff = fm >> 1;
    const int bKqOff   = fm & 1;

    const uint32_t sA0 = (uint32_t)__cvta_generic_to_shared(&sA[0][0]);
    const uint32_t sB0 = (uint32_t)__cvta_generic_to_shared(&sB[0][0]);

    auto issue = [&](int t) {
        if (t < ntiles) {
            const int buf = t % STG;
            const int k0  = t << 5;
            const uint32_t aBase = sA0 + buf * 8192;
            const uint32_t bBase = sB0 + buf * 8192;
            #pragma unroll
            for (int u = 0; u < 2; u++) {
                int cc = tid + u * 256;
                int row = cc >> 2, kq = cc & 3;
                cpasync16(aBase + (uint32_t)(ch16(row, kq) * 16),
                          A + (size_t)(m0 + row) * lda + k0 + kq * 8);
                cpasync16(bBase + (uint32_t)(ch16(row, kq) * 16),
                          Bg + (size_t)(n0 + row) * ldb + k0 + kq * 8);
            }
        }
        asm volatile("cp.async.commit_group;");
    };

    auto compute = [&](int buf) {
        const uint32_t aBase = sA0 + buf * 8192;
        const uint32_t bBase = sB0 + buf * 8192;
        #pragma unroll
        for (int ks = 0; ks < 2; ks++) {
            uint32_t a[4][4];
            uint32_t b[4][2];
            const int akq = ks * 2 + aKqOff;
            const int bkq = ks * 2 + bKqOff;
            #pragma unroll
            for (int i = 0; i < 4; i++) {
                uint32_t addr = aBase + (uint32_t)(ch16(aRowBase + i * 16, akq) * 16);
                ldsm4(a[i][0], a[i][1], a[i][2], a[i][3], addr);
            }
            #pragma unroll
            for (int j2 = 0; j2 < 4; j2 += 2) {
                int tile = wn * 4 + j2 + bTileOff;
                uint32_t addr = bBase + (uint32_t)(ch16(tile * 8 + fj, bkq) * 16);
                ldsm4(b[j2][0], b[j2][1], b[j2 + 1][0], b[j2 + 1][1], addr);
            }
            #pragma unroll
            for (int i = 0; i < 4; i++)
                #pragma unroll
                for (int j = 0; j < 4; j++)
                    mma16(acc[i][j], a[i], b[j]);
        }
    };

    issue(0);
    issue(1);
    for (int t = 0; t < ntiles; t++) {
        asm volatile("cp.async.wait_group 1;");
        __syncthreads();
        issue(t + 2);
        compute(t % STG);
    }

    #pragma unroll
    for (int i = 0; i < 4; i++) {
        int r0 = m0 + wm * 64 + i * 16 + (lane >> 2);
        #pragma unroll
        for (int j = 0; j < 4; j++) {
            int col = n0 + wn * 32 + j * 8 + ((lane & 3) << 1);
            float2 bb = *(const float2*)&bias[col];
            float v0 = acc[i][j][0] + bb.x, v1 = acc[i][j][1] + bb.y;
            float v2 = acc[i][j][2] + bb.x, v3 = acc[i][j][3] + bb.y;
            if (EPI == 1) { v0 *= scale; v1 *= scale; v2 *= scale; v3 *= scale; }
            if (EPI == 2) { v0 = gelu(v0); v1 = gelu(v1); v2 = gelu(v2); v3 = gelu(v3); }
            if (OUTH) {
                __half* C = (__half*)Cv;
                *(__half2*)&C[(size_t)r0 * ldc + col]       = __floats2half2_rn(v0, v1);
                *(__half2*)&C[(size_t)(r0 + 8) * ldc + col] = __floats2half2_rn(v2, v3);
            } else {
                float* C = (float*)Cv;
                *(float2*)&C[(size_t)r0 * ldc + col]       = make_float2(v0, v1);
                *(float2*)&C[(size_t)(r0 + 8) * ldc + col] = make_float2(v2, v3);
            }
        }
    }
}

// =====================================================================
// Fused attention, fp16: QK^T + mask + softmax + PV, flash recompute.
// 104KB dyn smem -> 2 CTAs/SM. sP double-buffered; PV(t-1) decoupled.
// bytes: sQ 0(16384) | sK 16384(3x8192) | sV 40960(3x8192)
//        sP 65536(2x16384) | fmask 98304(8192) | total 106496
// =====================================================================
#define AF_SMEM_BYTES 106496

__global__ __launch_bounds__(256, 2) void attn_fused(
    const __half* __restrict__ qg, const __half* __restrict__ kg,
    const __half* __restrict__ vg, const unsigned char* __restrict__ mask,
    float* __restrict__ probs, __half* __restrict__ aog)
{
    extern __shared__ char smc[];
    const int tid  = threadIdx.x;
    const int lane = tid & 31;
    const int w    = tid >> 5;
    const int wm   = w & 1;
    const int wn   = w >> 1;
    const int q0   = blockIdx.x * 128;
    const int z    = blockIdx.y;
    const int b    = z >> 4, hh = z & 15;
    const long long ld = (long long)BATCH * D;

    const __half* Q = qg + (size_t)b * D + hh * 64;
    const __half* K = kg + (size_t)b * D + hh * 64;
    const __half* V = vg + (size_t)b * D + hh * 64;
    float* P   = probs + (size_t)z * S * S;
    __half* AO = aog + (size_t)b * D + hh * 64;
    const unsigned char* MK = mask + (size_t)b * S;

    const uint32_t smb = (uint32_t)__cvta_generic_to_shared(smc);
    float* fmask = (float*)(smc + 98304);

    const int fm = lane >> 3;
    const int fj = lane & 7;
    const int aRowN    = w * 16 + (fm & 1) * 8 + fj;      // score A rows (warp band)
    const int aRowBase = wm * 64 + (fm & 1) * 8 + fj;     // PV A rows
    const int aKqOff   = fm >> 1;
    const int bTileOff = fm >> 1;
    const int bKqOff   = fm & 1;

    // mask -> smem float table
    #pragma unroll
    for (int u = 0; u < 8; u++) {
        int i = tid + u * 256;
        fmask[i] = MK[i] ? NEGV : 0.0f;
    }

    // stage Q once (128 rows x 8 chunks), folded into first commit
    #pragma unroll
    for (int u = 0; u < 4; u++) {
        int c = tid + u * 256;
        int row = c >> 3, kq = c & 7;
        cpasync16(smb + (uint32_t)(ch8(row, kq) * 16),
                  Q + (size_t)(q0 + row) * ld + kq * 8);
    }

    auto issueK = [&](int it) {
        if (it < 32) {
            const uint32_t kb = smb + 16384u + (uint32_t)((it % 3) * 8192);
            const int key0 = it * 64;
            #pragma unroll
            for (int u = 0; u < 2; u++) {
                int c = tid + u * 256;
                int key = c >> 3, kq = c & 7;
                cpasync16(kb + (uint32_t)(ch8(key, kq) * 16),
                          K + (size_t)(key0 + key) * ld + kq * 8);
            }
        }
        asm volatile("cp.async.commit_group;");
    };
    auto issueKV = [&](int it) {
        if (it < 32) {
            const uint32_t kb = smb + 16384u + (uint32_t)((it % 3) * 8192);
            const uint32_t vb = smb + 40960u + (uint32_t)((it % 3) * 8192);
            const int key0 = it * 64;
            #pragma unroll
            for (int u = 0; u < 2; u++) {
                int c = tid + u * 256;
                int key = c >> 3, kq = c & 7;
                cpasync16(kb + (uint32_t)(ch8(key, kq) * 16),
                          K + (size_t)(key0 + key) * ld + kq * 8);
                cpasync16(vb + (uint32_t)(ch8(key, kq) * 16),
                          V + (size_t)(key0 + key) * ld + kq * 8);
            }
        }
        asm volatile("cp.async.commit_group;");
    };

    // scores: warp band 16 rows x 64 keys; acc[j][c] as in round 8
    auto score = [&](int buf, float (&acc)[8][4]) {
        #pragma unroll
        for (int j = 0; j < 8; j++)
            #pragma unroll
            for (int c = 0; c < 4; c++) acc[j][c] = 0.f;
        const uint32_t kb = smb + 16384u + (uint32_t)(buf * 8192);
        #pragma unroll
        for (int ks = 0; ks < 4; ks++) {
            uint32_t a[4];
            uint32_t bfr[8][2];
            {
                uint32_t addr = smb + (uint32_t)(ch8(aRowN, ks * 2 + aKqOff) * 16);
                ldsm4(a[0], a[1], a[2], a[3], addr);
            }
            #pragma unroll
            for (int j2 = 0; j2 < 8; j2 += 2) {
                int tile = j2 + bTileOff;
                uint32_t addr = kb + (uint32_t)(ch8(tile * 8 + fj, ks * 2 + bKqOff) * 16);
                ldsm4(bfr[j2][0], bfr[j2][1], bfr[j2 + 1][0], bfr[j2 + 1][1], addr);
            }
            #pragma unroll
            for (int j = 0; j < 8; j++)
                mma16(acc[j], a, bfr[j]);
        }
    };

    float acc[8][4];
    float m0 = -1e30f, m1 = -1e30f, s0 = 0.f, s1 = 0.f;

    // ================= PASS A: register-resident row stats =================
    issueK(0);
    issueK(1);
    for (int it = 0; it < 32; it++) {
        asm volatile("cp.async.wait_group 1;");
        __syncthreads();
        issueK(it + 2);
        score(it % 3, acc);

        float2 fmj[8];
        #pragma unroll
        for (int j = 0; j < 8; j++)
            fmj[j] = *(const float2*)&fmask[it * 64 + j * 8 + ((lane & 3) << 1)];

        float mt0 = -1e30f, mt1 = -1e30f;
        #pragma unroll
        for (int j = 0; j < 8; j++) {
            mt0 = fmaxf(mt0, fmaxf(acc[j][0] + fmj[j].x, acc[j][1] + fmj[j].y));
            mt1 = fmaxf(mt1, fmaxf(acc[j][2] + fmj[j].x, acc[j][3] + fmj[j].y));
        }
        mt0 = fmaxf(mt0, __shfl_xor_sync(0xffffffffu, mt0, 1));
        mt0 = fmaxf(mt0, __shfl_xor_sync(0xffffffffu, mt0, 2));
        mt1 = fmaxf(mt1, __shfl_xor_sync(0xffffffffu, mt1, 1));
        mt1 = fmaxf(mt1, __shfl_xor_sync(0xffffffffu, mt1, 2));

        float mn0 = fmaxf(m0, mt0), mn1 = fmaxf(m1, mt1);
        float c0 = __expf(m0 - mn0), c1 = __expf(m1 - mn1);
        float ls0 = 0.f, ls1 = 0.f;
        #pragma unroll
        for (int j = 0; j < 8; j++) {
            ls0 += __expf(acc[j][0] + fmj[j].x - mn0) + __expf(acc[j][1] + fmj[j].y - mn0);
            ls1 += __expf(acc[j][2] + fmj[j].x - mn1) + __expf(acc[j][3] + fmj[j].y - mn1);
        }
        ls0 += __shfl_xor_sync(0xffffffffu, ls0, 1);
        ls0 += __shfl_xor_sync(0xffffffffu, ls0, 2);
        ls1 += __shfl_xor_sync(0xffffffffu, ls1, 1);
        ls1 += __shfl_xor_sync(0xffffffffu, ls1, 2);

        s0 = s0 * c0 + ls0;
        s1 = s1 * c1 + ls1;
        m0 = mn0; m1 = mn1;
    }

    const float inv0 = 1.0f / s0;
    const float inv1 = 1.0f / s1;

    // ================= PASS B: probs + PV (PV lags one tile) =================
    float O[4][2][4] = {};

    auto pv = [&](int t) {
        const uint32_t pb = smb + 65536u + (uint32_t)((t & 1) * 16384);
        const uint32_t vb = smb + 40960u + (uint32_t)((t % 3) * 8192);
        #pragma unroll
        for (int ks = 0; ks < 4; ks++) {
            uint32_t a[4][4];
            uint32_t bv[2][2];
            #pragma unroll
            for (int i = 0; i < 4; i++) {
                uint32_t addr = pb + (uint32_t)(ch8(aRowBase + i * 16, ks * 2 + aKqOff) * 16);
                ldsm4(a[i][0], a[i][1], a[i][2], a[i][3], addr);
            }
            {
                uint32_t addr = vb + (uint32_t)(ch8(16 * ks + (fm & 1) * 8 + fj,
                                                    wn * 2 + (fm >> 1)) * 16);
                ldsm4t(bv[0][0], bv[0][1], bv[1][0], bv[1][1], addr);
            }
            #pragma unroll
            for (int i = 0; i < 4; i++)
                #pragma unroll
                for (int j = 0; j < 2; j++)
                    mma16(O[i][j], a[i], bv[j]);
        }
    };

    issueKV(0);
    issueKV(1);
    for (int it = 0; it < 32; it++) {
        asm volatile("cp.async.wait_group 1;");
        __syncthreads();
        score(it % 3, acc);

        const int key0 = it * 64;
        const int r0l = w * 16 + (lane >> 2);
        const int r1l = r0l + 8;
        char* pB = smc + 65536 + (it & 1) * 16384;
        #pragma unroll
        for (int j = 0; j < 8; j++) {
            float2 fmv = *(const float2*)&fmask[key0 + j * 8 + ((lane & 3) << 1)];
            float p0 = __expf(acc[j][0] + fmv.x - m0) * inv0;
            float p1 = __expf(acc[j][1] + fmv.y - m0) * inv0;
            float p2 = __expf(acc[j][2] + fmv.x - m1) * inv1;
            float p3 = __expf(acc[j][3] + fmv.y - m1) * inv1;
            int keyloc = j * 8 + ((lane & 3) << 1);
            *(float2*)&P[(size_t)(q0 + r0l) * S + key0 + keyloc] = make_float2(p0, p1);
            *(float2*)&P[(size_t)(q0 + r1l) * S + key0 + keyloc] = make_float2(p2, p3);
            *(__half2*)(pB + ch8(r0l, j) * 16 + (lane & 3) * 4) = __floats2half2_rn(p0, p1);
            *(__half2*)(pB + ch8(r1l, j) * 16 + (lane & 3) * 4) = __floats2half2_rn(p2, p3);
        }

        if (it > 0) pv(it - 1);
        __syncthreads();        // PV(it-1) reads done before V[(it+2)%3] overwrite; sP(it) published
        issueKV(it + 2);
    }
    asm volatile("cp.async.wait_group 0;");
    pv(31);

    // ---- write O as fp16 for O-proj GEMM ----
    #pragma unroll
    for (int i = 0; i < 4; i++) {
        int r0 = q0 + wm * 64 + i * 16 + (lane >> 2);
        #pragma unroll
        for (int j = 0; j < 2; j++) {
            int col = wn * 16 + j * 8 + ((lane & 3) << 1);
            *(__half2*)&AO[(size_t)r0 * ld + col] =
                __floats2half2_rn(O[i][j][0], O[i][j][1]);
            *(__half2*)&AO[(size_t)(r0 + 8) * ld + col] =
                __floats2half2_rn(O[i][j][2], O[i][j][3]);
        }
    }
}

// ---------------- pre-pass: fp32 -> fp16 ----------------
__global__ __launch_bounds__(256) void round_half(const float* __restrict__ in,
                                                  __half* __restrict__ out, int n4)
{
    int i = blockIdx.x * 256 + threadIdx.x;
    if (i < n4) {
        float4 v = ((const float4*)in)[i];
        ((__half2*)out)[2*i]   = __floats2half2_rn(v.x, v.y);
        ((__half2*)out)[2*i+1] = __floats2half2_rn(v.z, v.w);
    }
}

// ---------------- pre-pass: transpose + fp16: out[N][K] = h(in[K][N]^T) ----------------
__global__ __launch_bounds__(256) void transpose_half(const float* __restrict__ in,
                                                      __half* __restrict__ out,
                                                      int K, int N)
{
    __shared__ float tile[32][33];
    int n = blockIdx.x * 32 + threadIdx.x;
    int k = blockIdx.y * 32 + threadIdx.y;
    #pragma unroll
    for (int i = 0; i < 32; i += 8)
        tile[threadIdx.y + i][threadIdx.x] = in[(size_t)(k + i) * N + n];
    __syncthreads();
    int n2 = blockIdx.x * 32 + threadIdx.y;
    int k2 = blockIdx.y * 32 + threadIdx.x;
    #pragma unroll
    for (int i = 0; i < 32; i += 8)
        out[(size_t)(n2 + i) * K + k2] = __float2half_rn(tile[threadIdx.x][threadIdx.y + i]);
}

// ---------------- layernorm(resid + y) * g + beta (+ optional fp16 copy) ----------------
__global__ __launch_bounds__(256) void ln_kernel(
    const float* __restrict__ resid, const float* __restrict__ y,
    const float* __restrict__ g, const float* __restrict__ beta,
    float* __restrict__ out, __half* __restrict__ out_r)
{
    const int row = blockIdx.x;
    const int tid = threadIdx.x;
    float4 a = ((const float4*)(resid + (size_t)row * D))[tid];
    float4 c = ((const float4*)(y + (size_t)row * D))[tid];
    float v0 = a.x + c.x, v1 = a.y + c.y, v2 = a.z + c.z, v3 = a.w + c.w;

    __shared__ float sh[256], sh2[256];
    sh[tid]  = v0 + v1 + v2 + v3;
    sh2[tid] = v0*v0 + v1*v1 + v2*v2 + v3*v3;
    __syncthreads();
    for (int st = 128; st > 0; st >>= 1) {
        if (tid < st) { sh[tid] += sh[tid + st]; sh2[tid] += sh2[tid + st]; }
        __syncthreads();
    }
    float mean = sh[0] * (1.0f / D);
    float var  = sh2[0] * (1.0f / D) - mean * mean;
    float rstd = rsqrtf(var + 1e-5f);

    float4 g4 = ((const float4*)g)[tid];
    float4 b4 = ((const float4*)beta)[tid];
    float4 o;
    o.x = (v0 - mean) * rstd * g4.x + b4.x;
    o.y = (v1 - mean) * rstd * g4.y + b4.y;
    o.z = (v2 - mean) * rstd * g4.z + b4.z;
    o.w = (v3 - mean) * rstd * g4.w + b4.w;
    ((float4*)(out + (size_t)row * D))[tid] = o;
    if (out_r) {
        __half2* hr = (__half2*)(out_r + (size_t)row * D);
        hr[2*tid]   = __floats2half2_rn(o.x, o.y);
        hr[2*tid+1] = __floats2half2_rn(o.z, o.w);
    }
}

// ---------------- launcher ----------------
extern "C" void kernel_launch(void* const* d_in, const int* in_sizes, int n_in,
                              void* d_out, int out_size)
{
    const float* x    = (const float*)d_in[0];
    const unsigned char* mask = (const unsigned char*)d_in[1];
    const float* Wq   = (const float*)d_in[2];
    const float* bq   = (const float*)d_in[3];
    const float* Wk   = (const float*)d_in[4];
    const float* bk   = (const float*)d_in[5];
    const float* Wv   = (const float*)d_in[6];
    const float* bv   = (const float*)d_in[7];
    const float* Wo   = (const float*)d_in[8];
    const float* bo   = (const float*)d_in[9];
    const float* ln1g = (const float*)d_in[10];
    const float* ln1b = (const float*)d_in[11];
    const float* W1   = (const float*)d_in[12];
    const float* b1   = (const float*)d_in[13];
    const float* W2   = (const float*)d_in[14];
    const float* b2   = (const float*)d_in[15];
    const float* ln2g = (const float*)d_in[16];
    const float* ln2b = (const float*)d_in[17];

    __half *q, *k, *v, *ao, *x1r, *h, *xr, *wqt, *wkt, *wvt, *wot, *w1t, *w2t;
    float *x1, *y, *attn;
    cudaGetSymbolAddress((void**)&q,   g_q);
    cudaGetSymbolAddress((void**)&k,   g_k);
    cudaGetSymbolAddress((void**)&v,   g_v);
    cudaGetSymbolAddress((void**)&ao,  g_ao);
    cudaGetSymbolAddress((void**)&x1,  g_x1);
    cudaGetSymbolAddress((void**)&x1r, g_x1r);
    cudaGetSymbolAddress((void**)&y,   g_y);
    cudaGetSymbolAddress((void**)&h,   g_h);
    cudaGetSymbolAddress((void**)&attn, g_attn);
    cudaGetSymbolAddress((void**)&xr,  g_xr);
    cudaGetSymbolAddress((void**)&wqt, g_wqt);
    cudaGetSymbolAddress((void**)&wkt, g_wkt);
    cudaGetSymbolAddress((void**)&wvt, g_wvt);
    cudaGetSymbolAddress((void**)&wot, g_wot);
    cudaGetSymbolAddress((void**)&w1t, g_w1t);
    cudaGetSymbolAddress((void**)&w2t, g_w2t);

    const long long X  = (long long)T * D;
    const long long AW = (long long)BATCH * H * (long long)S * S;
    float* xout;
    float* attnout;
    if ((long long)out_size >= X + AW) {
        xout = (float*)d_out;
        attnout = (float*)d_out + X;
    } else if ((long long)out_size == AW) {
        attnout = (float*)d_out;
        xout = attn;                 // dummy fp32 scratch
    } else {
        xout = (float*)d_out;
        attnout = attn;
    }

    static int af_attr_set = 0;
    if (!af_attr_set) {
        cudaFuncSetAttribute(attn_fused,
                             cudaFuncAttributeMaxDynamicSharedMemorySize, AF_SMEM_BYTES);
        af_attr_set = 1;
    }

    dim3 blk(256);
    dim3 tb(32, 8);
    const float scaling = 0.125f;

    // ---- pre-pass: convert x; transpose+convert weights ----
    round_half<<<dim3((T*D/4 + 255)/256), blk>>>(x, xr, T*D/4);
    transpose_half<<<dim3(D/32, D/32), tb>>>(Wq, wqt, D, D);
    transpose_half<<<dim3(D/32, D/32), tb>>>(Wk, wkt, D, D);
    transpose_half<<<dim3(D/32, D/32), tb>>>(Wv, wvt, D, D);
    transpose_half<<<dim3(D/32, D/32), tb>>>(Wo, wot, D, D);
    transpose_half<<<dim3(FFN_DIM/32, D/32), tb>>>(W1, w1t, D, FFN_DIM);
    transpose_half<<<dim3(D/32, FFN_DIM/32), tb>>>(W2, w2t, FFN_DIM, D);

    // ---- QKV projections ----
    hgemm<1,true><<<dim3(D/128, T/128), blk>>>(xr, D, wqt, D, bq, q, D, D, scaling);
    hgemm<0,true><<<dim3(D/128, T/128), blk>>>(xr, D, wkt, D, bk, k, D, D, 1.0f);
    hgemm<0,true><<<dim3(D/128, T/128), blk>>>(xr, D, wvt, D, bv, v, D, D, 1.0f);

    // ---- fused attention ----
    attn_fused<<<dim3(S/128, BATCH*H), blk, AF_SMEM_BYTES>>>(q, k, v, mask, attnout, ao);

    // ---- O-proj + LN1 ----
    hgemm<0,false><<<dim3(D/128, T/128), blk>>>(ao, D, wot, D, bo, y, D, D, 1.0f);
    ln_kernel<<<dim3(T), blk>>>(x, y, ln1g, ln1b, x1, x1r);

    // ---- FFN + LN2 ----
    hgemm<2,true><<<dim3(FFN_DIM/128, T/128), blk>>>(x1r, D, w1t, D, b1, h, FFN_DIM, D, 1.0f);
    hgemm<0,false><<<dim3(D/128, T/128), blk>>>(h, FFN_DIM, w2t, FFN_DIM, b2, y, D, FFN_DIM, 1.0f);
    ln_kernel<<<dim3(T), blk>>>(x1, y, ln2g, ln2b, xout, nullptr);
}

// round 10
// speedup vs baseline: 1.8001x; 1.0261x over previous
#include <cuda_runtime.h>
#include <cuda_fp16.h>
#include <math.h>
#include <stdint.h>

#define S 2048
#define BATCH 2
#define D 1024
#define H 16
#define FFN_DIM 4096
#define T (S*BATCH)
#define NEGV -1e9f
#define QKV_LD 3072

// ---------------- scratch (device globals; no allocation allowed) ----------------
__device__ __half g_qkv[(size_t)T*3*D];
__device__ __half g_ao[(size_t)T*D];
__device__ float  g_x1[(size_t)T*D];
__device__ __half g_x1r[(size_t)T*D];
__device__ float  g_y[(size_t)T*D];
__device__ __half g_h[(size_t)T*FFN_DIM];
__device__ float  g_attn[(size_t)BATCH*H*S*S];   // fallback buffers only
__device__ __half g_xr[(size_t)T*D];
__device__ __half g_wqkvt[(size_t)3*D*D];
__device__ __half g_wot[(size_t)D*D];
__device__ __half g_w1t[(size_t)D*FFN_DIM];
__device__ __half g_w2t[(size_t)D*FFN_DIM];
__device__ float  g_bqkv[3*D];

// ---------------- helpers ----------------
__device__ __forceinline__ void mma16(float* c, const uint32_t* a, const uint32_t* b) {
    asm("mma.sync.aligned.m16n8k16.row.col.f32.f16.f16.f32 "
        "{%0,%1,%2,%3},{%4,%5,%6,%7},{%8,%9},{%0,%1,%2,%3};"
        : "+f"(c[0]), "+f"(c[1]), "+f"(c[2]), "+f"(c[3])
        : "r"(a[0]), "r"(a[1]), "r"(a[2]), "r"(a[3]),
          "r"(b[0]), "r"(b[1]));
}

__device__ __forceinline__ void ldsm4(uint32_t& r0, uint32_t& r1, uint32_t& r2, uint32_t& r3,
                                      uint32_t addr) {
    asm volatile("ldmatrix.sync.aligned.m8n8.x4.shared.b16 {%0,%1,%2,%3}, [%4];"
                 : "=r"(r0), "=r"(r1), "=r"(r2), "=r"(r3) : "r"(addr));
}

__device__ __forceinline__ void ldsm4t(uint32_t& r0, uint32_t& r1, uint32_t& r2, uint32_t& r3,
                                       uint32_t addr) {
    asm volatile("ldmatrix.sync.aligned.m8n8.x4.trans.shared.b16 {%0,%1,%2,%3}, [%4];"
                 : "=r"(r0), "=r"(r1), "=r"(r2), "=r"(r3) : "r"(addr));
}

__device__ __forceinline__ void cpasync16(uint32_t dst, const void* src) {
    asm volatile("cp.async.cg.shared.global [%0], [%1], 16;" :: "r"(dst), "l"(src));
}

__device__ __forceinline__ int ch16(int row, int kq) {        // GEMM: 4 chunks/row
    return row * 4 + (kq ^ ((row >> 1) & 3));
}
__device__ __forceinline__ int ch8(int r, int q) {            // attention: 8 chunks/row
    return r * 8 + (q ^ (r & 7));
}

__device__ __forceinline__ float gelu(float v) {
    return 0.5f * v * (1.0f + erff(v * 0.70710678118654752f));
}

// =====================================================================
// fp16 cp.async 3-stage GEMM: C[M,N] = A[M,K]@B^T + bias (B given [N][K]).
// BM=128, BN=128, BK=32, 256 threads (8 warps, 2m x 4n).
// EPI: 0=bias, 1=bias*scale, 2=gelu(bias), 3=QKV (scale cols < D only).
// OUTH: write __half else float.
// =====================================================================
template<int EPI, bool OUTH>
__global__ __launch_bounds__(256, 2) void hgemm(
    const __half* __restrict__ A, long long lda,
    const __half* __restrict__ Bg, long long ldb,
    const float* __restrict__ bias,
    void* __restrict__ Cv, long long ldc,
    int K, float scale)
{
    constexpr int STG = 3;
    __shared__ __half sA[STG][128 * 32];
    __shared__ __half sB[STG][128 * 32];

    const int tid  = threadIdx.x;
    const int lane = tid & 31;
    const int w    = tid >> 5;
    const int wm   = w & 1;
    const int wn   = w >> 1;
    const int m0   = blockIdx.y * 128;
    const int n0   = blockIdx.x * 128;

    float acc[4][4][4] = {};
    const int ntiles = K >> 5;

    const int fm = lane >> 3;
    const int fj = lane & 7;
    const int aRowBase = wm * 64 + (fm & 1) * 8 + fj;
    const int aKqOff   = fm >> 1;
    const int bTileOff = fm >> 1;
    const int bKqOff   = fm & 1;

    const uint32_t sA0 = (uint32_t)__cvta_generic_to_shared(&sA[0][0]);
    const uint32_t sB0 = (uint32_t)__cvta_generic_to_shared(&sB[0][0]);

    auto issue = [&](int t) {
        if (t < ntiles) {
            const int buf = t % STG;
            const int k0  = t << 5;
            const uint32_t aBase = sA0 + buf * 8192;
            const uint32_t bBase = sB0 + buf * 8192;
            #pragma unroll
            for (int u = 0; u < 2; u++) {
                int cc = tid + u * 256;
                int row = cc >> 2, kq = cc & 3;
                cpasync16(aBase + (uint32_t)(ch16(row, kq) * 16),
                          A + (size_t)(m0 + row) * lda + k0 + kq * 8);
                cpasync16(bBase + (uint32_t)(ch16(row, kq) * 16),
                          Bg + (size_t)(n0 + row) * ldb + k0 + kq * 8);
            }
        }
        asm volatile("cp.async.commit_group;");
    };

    auto compute = [&](int buf) {
        const uint32_t aBase = sA0 + buf * 8192;
        const uint32_t bBase = sB0 + buf * 8192;
        #pragma unroll
        for (int ks = 0; ks < 2; ks++) {
            uint32_t a[4][4];
            uint32_t b[4][2];
            const int akq = ks * 2 + aKqOff;
            const int bkq = ks * 2 + bKqOff;
            #pragma unroll
            for (int i = 0; i < 4; i++) {
                uint32_t addr = aBase + (uint32_t)(ch16(aRowBase + i * 16, akq) * 16);
                ldsm4(a[i][0], a[i][1], a[i][2], a[i][3], addr);
            }
            #pragma unroll
            for (int j2 = 0; j2 < 4; j2 += 2) {
                int tile = wn * 4 + j2 + bTileOff;
                uint32_t addr = bBase + (uint32_t)(ch16(tile * 8 + fj, bkq) * 16);
                ldsm4(b[j2][0], b[j2][1], b[j2 + 1][0], b[j2 + 1][1], addr);
            }
            #pragma unroll
            for (int i = 0; i < 4; i++)
                #pragma unroll
                for (int j = 0; j < 4; j++)
                    mma16(acc[i][j], a[i], b[j]);
        }
    };

    issue(0);
    issue(1);
    for (int t = 0; t < ntiles; t++) {
        asm volatile("cp.async.wait_group 1;");
        __syncthreads();
        issue(t + 2);
        compute(t % STG);
    }

    // EPI==3: scale only q columns (n0 uniform per block, D multiple of 128)
    const float sc = (EPI == 1) ? scale : (EPI == 3 ? (n0 < D ? scale : 1.0f) : 1.0f);

    #pragma unroll
    for (int i = 0; i < 4; i++) {
        int r0 = m0 + wm * 64 + i * 16 + (lane >> 2);
        #pragma unroll
        for (int j = 0; j < 4; j++) {
            int col = n0 + wn * 32 + j * 8 + ((lane & 3) << 1);
            float2 bb = *(const float2*)&bias[col];
            float v0 = acc[i][j][0] + bb.x, v1 = acc[i][j][1] + bb.y;
            float v2 = acc[i][j][2] + bb.x, v3 = acc[i][j][3] + bb.y;
            if (EPI == 1 || EPI == 3) { v0 *= sc; v1 *= sc; v2 *= sc; v3 *= sc; }
            if (EPI == 2) { v0 = gelu(v0); v1 = gelu(v1); v2 = gelu(v2); v3 = gelu(v3); }
            if (OUTH) {
                __half* C = (__half*)Cv;
                *(__half2*)&C[(size_t)r0 * ldc + col]       = __floats2half2_rn(v0, v1);
                *(__half2*)&C[(size_t)(r0 + 8) * ldc + col] = __floats2half2_rn(v2, v3);
            } else {
                float* C = (float*)Cv;
                *(float2*)&C[(size_t)r0 * ldc + col]       = make_float2(v0, v1);
                *(float2*)&C[(size_t)(r0 + 8) * ldc + col] = make_float2(v2, v3);
            }
        }
    }
}

// =====================================================================
// Fused attention, fp16 (round-9 structure, QKV packed source, __stcs P).
// bytes: sQ 0(16384) | sK 16384(3x8192) | sV 40960(3x8192)
//        sP 65536(2x16384) | fmask 98304(8192) | total 106496
// =====================================================================
#define AF_SMEM_BYTES 106496

__global__ __launch_bounds__(256, 2) void attn_fused(
    const __half* __restrict__ qkv, const unsigned char* __restrict__ mask,
    float* __restrict__ probs, __half* __restrict__ aog)
{
    extern __shared__ char smc[];
    const int tid  = threadIdx.x;
    const int lane = tid & 31;
    const int w    = tid >> 5;
    const int wm   = w & 1;
    const int wn   = w >> 1;
    const int q0   = blockIdx.x * 128;
    const int z    = blockIdx.y;
    const int b    = z >> 4, hh = z & 15;
    const long long ld  = (long long)BATCH * QKV_LD;   // 6144
    const long long ldo = (long long)BATCH * D;        // 2048

    const __half* Q = qkv + (size_t)b * QKV_LD + hh * 64;
    const __half* K = Q + D;
    const __half* V = Q + 2 * D;
    float* P   = probs + (size_t)z * S * S;
    __half* AO = aog + (size_t)b * D + hh * 64;
    const unsigned char* MK = mask + (size_t)b * S;

    const uint32_t smb = (uint32_t)__cvta_generic_to_shared(smc);
    float* fmask = (float*)(smc + 98304);

    const int fm = lane >> 3;
    const int fj = lane & 7;
    const int aRowN    = w * 16 + (fm & 1) * 8 + fj;
    const int aRowBase = wm * 64 + (fm & 1) * 8 + fj;
    const int aKqOff   = fm >> 1;
    const int bTileOff = fm >> 1;
    const int bKqOff   = fm & 1;

    #pragma unroll
    for (int u = 0; u < 8; u++) {
        int i = tid + u * 256;
        fmask[i] = MK[i] ? NEGV : 0.0f;
    }

    #pragma unroll
    for (int u = 0; u < 4; u++) {
        int c = tid + u * 256;
        int row = c >> 3, kq = c & 7;
        cpasync16(smb + (uint32_t)(ch8(row, kq) * 16),
                  Q + (size_t)(q0 + row) * ld + kq * 8);
    }

    auto issueK = [&](int it) {
        if (it < 32) {
            const uint32_t kb = smb + 16384u + (uint32_t)((it % 3) * 8192);
            const int key0 = it * 64;
            #pragma unroll
            for (int u = 0; u < 2; u++) {
                int c = tid + u * 256;
                int key = c >> 3, kq = c & 7;
                cpasync16(kb + (uint32_t)(ch8(key, kq) * 16),
                          K + (size_t)(key0 + key) * ld + kq * 8);
            }
        }
        asm volatile("cp.async.commit_group;");
    };
    auto issueKV = [&](int it) {
        if (it < 32) {
            const uint32_t kb = smb + 16384u + (uint32_t)((it % 3) * 8192);
            const uint32_t vb = smb + 40960u + (uint32_t)((it % 3) * 8192);
            const int key0 = it * 64;
            #pragma unroll
            for (int u = 0; u < 2; u++) {
                int c = tid + u * 256;
                int key = c >> 3, kq = c & 7;
                cpasync16(kb + (uint32_t)(ch8(key, kq) * 16),
                          K + (size_t)(key0 + key) * ld + kq * 8);
                cpasync16(vb + (uint32_t)(ch8(key, kq) * 16),
                          V + (size_t)(key0 + key) * ld + kq * 8);
            }
        }
        asm volatile("cp.async.commit_group;");
    };

    auto score = [&](int buf, float (&acc)[8][4]) {
        #pragma unroll
        for (int j = 0; j < 8; j++)
            #pragma unroll
            for (int c = 0; c < 4; c++) acc[j][c] = 0.f;
        const uint32_t kb = smb + 16384u + (uint32_t)(buf * 8192);
        #pragma unroll
        for (int ks = 0; ks < 4; ks++) {
            uint32_t a[4];
            uint32_t bfr[8][2];
            {
                uint32_t addr = smb + (uint32_t)(ch8(aRowN, ks * 2 + aKqOff) * 16);
                ldsm4(a[0], a[1], a[2], a[3], addr);
            }
            #pragma unroll
            for (int j2 = 0; j2 < 8; j2 += 2) {
                int tile = j2 + bTileOff;
                uint32_t addr = kb + (uint32_t)(ch8(tile * 8 + fj, ks * 2 + bKqOff) * 16);
                ldsm4(bfr[j2][0], bfr[j2][1], bfr[j2 + 1][0], bfr[j2 + 1][1], addr);
            }
            #pragma unroll
            for (int j = 0; j < 8; j++)
                mma16(acc[j], a, bfr[j]);
        }
    };

    float acc[8][4];
    float m0 = -1e30f, m1 = -1e30f, s0 = 0.f, s1 = 0.f;

    // ================= PASS A: register-resident row stats =================
    issueK(0);
    issueK(1);
    for (int it = 0; it < 32; it++) {
        asm volatile("cp.async.wait_group 1;");
        __syncthreads();
        issueK(it + 2);
        score(it % 3, acc);

        float2 fmj[8];
        #pragma unroll
        for (int j = 0; j < 8; j++)
            fmj[j] = *(const float2*)&fmask[it * 64 + j * 8 + ((lane & 3) << 1)];

        float mt0 = -1e30f, mt1 = -1e30f;
        #pragma unroll
        for (int j = 0; j < 8; j++) {
            mt0 = fmaxf(mt0, fmaxf(acc[j][0] + fmj[j].x, acc[j][1] + fmj[j].y));
            mt1 = fmaxf(mt1, fmaxf(acc[j][2] + fmj[j].x, acc[j][3] + fmj[j].y));
        }
        mt0 = fmaxf(mt0, __shfl_xor_sync(0xffffffffu, mt0, 1));
        mt0 = fmaxf(mt0, __shfl_xor_sync(0xffffffffu, mt0, 2));
        mt1 = fmaxf(mt1, __shfl_xor_sync(0xffffffffu, mt1, 1));
        mt1 = fmaxf(mt1, __shfl_xor_sync(0xffffffffu, mt1, 2));

        float mn0 = fmaxf(m0, mt0), mn1 = fmaxf(m1, mt1);
        float c0 = __expf(m0 - mn0), c1 = __expf(m1 - mn1);
        float ls0 = 0.f, ls1 = 0.f;
        #pragma unroll
        for (int j = 0; j < 8; j++) {
            ls0 += __expf(acc[j][0] + fmj[j].x - mn0) + __expf(acc[j][1] + fmj[j].y - mn0);
            ls1 += __expf(acc[j][2] + fmj[j].x - mn1) + __expf(acc[j][3] + fmj[j].y - mn1);
        }
        ls0 += __shfl_xor_sync(0xffffffffu, ls0, 1);
        ls0 += __shfl_xor_sync(0xffffffffu, ls0, 2);
        ls1 += __shfl_xor_sync(0xffffffffu, ls1, 1);
        ls1 += __shfl_xor_sync(0xffffffffu, ls1, 2);

        s0 = s0 * c0 + ls0;
        s1 = s1 * c1 + ls1;
        m0 = mn0; m1 = mn1;
    }

    const float inv0 = 1.0f / s0;
    const float inv1 = 1.0f / s1;

    // ================= PASS B: probs + PV (PV lags one tile) =================
    float O[4][2][4] = {};

    auto pv = [&](int t) {
        const uint32_t pb = smb + 65536u + (uint32_t)((t & 1) * 16384);
        const uint32_t vb = smb + 40960u + (uint32_t)((t % 3) * 8192);
        #pragma unroll
        for (int ks = 0; ks < 4; ks++) {
            uint32_t a[4][4];
            uint32_t bv[2][2];
            #pragma unroll
            for (int i = 0; i < 4; i++) {
                uint32_t addr = pb + (uint32_t)(ch8(aRowBase + i * 16, ks * 2 + aKqOff) * 16);
                ldsm4(a[i][0], a[i][1], a[i][2], a[i][3], addr);
            }
            {
                uint32_t addr = vb + (uint32_t)(ch8(16 * ks + (fm & 1) * 8 + fj,
                                                    wn * 2 + (fm >> 1)) * 16);
                ldsm4t(bv[0][0], bv[0][1], bv[1][0], bv[1][1], addr);
            }
            #pragma unroll
            for (int i = 0; i < 4; i++)
                #pragma unroll
                for (int j = 0; j < 2; j++)
                    mma16(O[i][j], a[i], bv[j]);
        }
    };

    issueKV(0);
    issueKV(1);
    for (int it = 0; it < 32; it++) {
        asm volatile("cp.async.wait_group 1;");
        __syncthreads();
        score(it % 3, acc);

        const int key0 = it * 64;
        const int r0l = w * 16 + (lane >> 2);
        const int r1l = r0l + 8;
        char* pB = smc + 65536 + (it & 1) * 16384;
        #pragma unroll
        for (int j = 0; j < 8; j++) {
            float2 fmv = *(const float2*)&fmask[key0 + j * 8 + ((lane & 3) << 1)];
            float p0 = __expf(acc[j][0] + fmv.x - m0) * inv0;
            float p1 = __expf(acc[j][1] + fmv.y - m0) * inv0;
            float p2 = __expf(acc[j][2] + fmv.x - m1) * inv1;
            float p3 = __expf(acc[j][3] + fmv.y - m1) * inv1;
            int keyloc = j * 8 + ((lane & 3) << 1);
            __stcs((float2*)&P[(size_t)(q0 + r0l) * S + key0 + keyloc], make_float2(p0, p1));
            __stcs((float2*)&P[(size_t)(q0 + r1l) * S + key0 + keyloc], make_float2(p2, p3));
            *(__half2*)(pB + ch8(r0l, j) * 16 + (lane & 3) * 4) = __floats2half2_rn(p0, p1);
            *(__half2*)(pB + ch8(r1l, j) * 16 + (lane & 3) * 4) = __floats2half2_rn(p2, p3);
        }

        if (it > 0) pv(it - 1);
        __syncthreads();
        issueKV(it + 2);
    }
    asm volatile("cp.async.wait_group 0;");
    pv(31);

    #pragma unroll
    for (int i = 0; i < 4; i++) {
        int r0 = q0 + wm * 64 + i * 16 + (lane >> 2);
        #pragma unroll
        for (int j = 0; j < 2; j++) {
            int col = wn * 16 + j * 8 + ((lane & 3) << 1);
            *(__half2*)&AO[(size_t)r0 * ldo + col] =
                __floats2half2_rn(O[i][j][0], O[i][j][1]);
            *(__half2*)&AO[(size_t)(r0 + 8) * ldo + col] =
                __floats2half2_rn(O[i][j][2], O[i][j][3]);
        }
    }
}

// =====================================================================
// ONE fused pre-pass kernel (segmented by blockIdx.x):
//  [0,1024)      Wq -> wqkvt rows [0,1024)
//  [1024,2048)   Wk -> wqkvt rows [1024,2048)
//  [2048,3072)   Wv -> wqkvt rows [2048,3072)
//  [3072,4096)   Wo -> wot
//  [4096,8192)   W1 -> w1t   (K=1024, N=4096)
//  [8192,12288)  W2 -> w2t   (K=4096, N=1024)
//  [12288,13312) x  -> xr    (fp32 -> fp16 copy)
//  [13312,13324) bias concat -> bqkv
// =====================================================================
__device__ __forceinline__ void tile_transpose_h(
    const float* __restrict__ in, __half* __restrict__ out,
    int K, int N, int t, int tx, int ty)
{
    __shared__ float tile[32][33];
    int nt = N / 32;
    int n = (t % nt) * 32 + tx;
    int k = (t / nt) * 32 + ty;
    #pragma unroll
    for (int i = 0; i < 32; i += 8)
        tile[ty + i][tx] = in[(size_t)(k + i) * N + n];
    __syncthreads();
    int n2 = (t % nt) * 32 + ty;
    int k2 = (t / nt) * 32 + tx;
    #pragma unroll
    for (int i = 0; i < 32; i += 8)
        out[(size_t)(n2 + i) * K + k2] = __float2half_rn(tile[tx][ty + i]);
}

__global__ void prep_all(
    const float* __restrict__ Wq, const float* __restrict__ Wk,
    const float* __restrict__ Wv, const float* __restrict__ Wo,
    const float* __restrict__ W1, const float* __restrict__ W2,
    const float* __restrict__ x,
    const float* __restrict__ bq, const float* __restrict__ bk,
    const float* __restrict__ bv,
    __half* __restrict__ wqkvt, __half* __restrict__ wot,
    __half* __restrict__ w1t, __half* __restrict__ w2t,
    __half* __restrict__ xr, float* __restrict__ bqkv)
{
    const int bz = blockIdx.x;
    const int tx = threadIdx.x, ty = threadIdx.y;
    const int tid = ty * 32 + tx;

    if (bz < 1024) {
        tile_transpose_h(Wq, wqkvt, D, D, bz, tx, ty);
    } else if (bz < 2048) {
        tile_transpose_h(Wk, wqkvt + (size_t)D * D, D, D, bz - 1024, tx, ty);
    } else if (bz < 3072) {
        tile_transpose_h(Wv, wqkvt + (size_t)2 * D * D, D, D, bz - 2048, tx, ty);
    } else if (bz < 4096) {
        tile_transpose_h(Wo, wot, D, D, bz - 3072, tx, ty);
    } else if (bz < 8192) {
        tile_transpose_h(W1, w1t, D, FFN_DIM, bz - 4096, tx, ty);
    } else if (bz < 12288) {
        tile_transpose_h(W2, w2t, FFN_DIM, D, bz - 8192, tx, ty);
    } else if (bz < 13312) {
        int base = (bz - 12288) * 1024;   // in float4 units
        #pragma unroll
        for (int u = 0; u < 4; u++) {
            int i = base + tid + u * 256;
            float4 v = ((const float4*)x)[i];
            ((__half2*)xr)[2*i]   = __floats2half2_rn(v.x, v.y);
            ((__half2*)xr)[2*i+1] = __floats2half2_rn(v.z, v.w);
        }
    } else {
        int i = (bz - 13312) * 256 + tid;
        bqkv[i] = (i < D) ? bq[i] : (i < 2*D) ? bk[i - D] : bv[i - 2*D];
    }
}

// ---------------- layernorm(resid + y) * g + beta (+ optional fp16 copy) ----------------
__global__ __launch_bounds__(256) void ln_kernel(
    const float* __restrict__ resid, const float* __restrict__ y,
    const float* __restrict__ g, const float* __restrict__ beta,
    float* __restrict__ out, __half* __restrict__ out_r)
{
    const int row = blockIdx.x;
    const int tid = threadIdx.x;
    float4 a = ((const float4*)(resid + (size_t)row * D))[tid];
    float4 c = ((const float4*)(y + (size_t)row * D))[tid];
    float v0 = a.x + c.x, v1 = a.y + c.y, v2 = a.z + c.z, v3 = a.w + c.w;

    __shared__ float sh[256], sh2[256];
    sh[tid]  = v0 + v1 + v2 + v3;
    sh2[tid] = v0*v0 + v1*v1 + v2*v2 + v3*v3;
    __syncthreads();
    for (int st = 128; st > 0; st >>= 1) {
        if (tid < st) { sh[tid] += sh[tid + st]; sh2[tid] += sh2[tid + st]; }
        __syncthreads();
    }
    float mean = sh[0] * (1.0f / D);
    float var  = sh2[0] * (1.0f / D) - mean * mean;
    float rstd = rsqrtf(var + 1e-5f);

    float4 g4 = ((const float4*)g)[tid];
    float4 b4 = ((const float4*)beta)[tid];
    float4 o;
    o.x = (v0 - mean) * rstd * g4.x + b4.x;
    o.y = (v1 - mean) * rstd * g4.y + b4.y;
    o.z = (v2 - mean) * rstd * g4.z + b4.z;
    o.w = (v3 - mean) * rstd * g4.w + b4.w;
    ((float4*)(out + (size_t)row * D))[tid] = o;
    if (out_r) {
        __half2* hr = (__half2*)(out_r + (size_t)row * D);
        hr[2*tid]   = __floats2half2_rn(o.x, o.y);
        hr[2*tid+1] = __floats2half2_rn(o.z, o.w);
    }
}

// ---------------- launcher ----------------
extern "C" void kernel_launch(void* const* d_in, const int* in_sizes, int n_in,
                              void* d_out, int out_size)
{
    const float* x    = (const float*)d_in[0];
    const unsigned char* mask = (const unsigned char*)d_in[1];
    const float* Wq   = (const float*)d_in[2];
    const float* bq   = (const float*)d_in[3];
    const float* Wk   = (const float*)d_in[4];
    const float* bk   = (const float*)d_in[5];
    const float* Wv   = (const float*)d_in[6];
    const float* bv   = (const float*)d_in[7];
    const float* Wo   = (const float*)d_in[8];
    const float* bo   = (const float*)d_in[9];
    const float* ln1g = (const float*)d_in[10];
    const float* ln1b = (const float*)d_in[11];
    const float* W1   = (const float*)d_in[12];
    const float* b1   = (const float*)d_in[13];
    const float* W2   = (const float*)d_in[14];
    const float* b2   = (const float*)d_in[15];
    const float* ln2g = (const float*)d_in[16];
    const float* ln2b = (const float*)d_in[17];

    __half *qkv, *ao, *x1r, *h, *xr, *wqkvt, *wot, *w1t, *w2t;
    float *x1, *y, *attn, *bqkv;
    cudaGetSymbolAddress((void**)&qkv, g_qkv);
    cudaGetSymbolAddress((void**)&ao,  g_ao);
    cudaGetSymbolAddress((void**)&x1,  g_x1);
    cudaGetSymbolAddress((void**)&x1r, g_x1r);
    cudaGetSymbolAddress((void**)&y,   g_y);
    cudaGetSymbolAddress((void**)&h,   g_h);
    cudaGetSymbolAddress((void**)&attn, g_attn);
    cudaGetSymbolAddress((void**)&xr,  g_xr);
    cudaGetSymbolAddress((void**)&wqkvt, g_wqkvt);
    cudaGetSymbolAddress((void**)&wot, g_wot);
    cudaGetSymbolAddress((void**)&w1t, g_w1t);
    cudaGetSymbolAddress((void**)&w2t, g_w2t);
    cudaGetSymbolAddress((void**)&bqkv, g_bqkv);

    const long long X  = (long long)T * D;
    const long long AW = (long long)BATCH * H * (long long)S * S;
    float* xout;
    float* attnout;
    if ((long long)out_size >= X + AW) {
        xout = (float*)d_out;
        attnout = (float*)d_out + X;
    } else if ((long long)out_size == AW) {
        attnout = (float*)d_out;
        xout = attn;
    } else {
        xout = (float*)d_out;
        attnout = attn;
    }

    static int af_attr_set = 0;
    if (!af_attr_set) {
        cudaFuncSetAttribute(attn_fused,
                             cudaFuncAttributeMaxDynamicSharedMemorySize, AF_SMEM_BYTES);
        af_attr_set = 1;
    }

    dim3 blk(256);
    const float scaling = 0.125f;

    // ---- fused pre-pass (1 launch) ----
    prep_all<<<dim3(13324), dim3(32, 8)>>>(Wq, Wk, Wv, Wo, W1, W2, x,
                                           bq, bk, bv,
                                           wqkvt, wot, w1t, w2t, xr, bqkv);

    // ---- merged QKV projection: [T,1024] @ [3072,1024]^T ----
    hgemm<3,true><<<dim3(3*D/128, T/128), blk>>>(xr, D, wqkvt, D, bqkv, qkv, QKV_LD, D, scaling);

    // ---- fused attention ----
    attn_fused<<<dim3(S/128, BATCH*H), blk, AF_SMEM_BYTES>>>(qkv, mask, attnout, ao);

    // ---- O-proj + LN1 ----
    hgemm<0,false><<<dim3(D/128, T/128), blk>>>(ao, D, wot, D, bo, y, D, D, 1.0f);
    ln_kernel<<<dim3(T), blk>>>(x, y, ln1g, ln1b, x1, x1r);

    // ---- FFN + LN2 ----
    hgemm<2,true><<<dim3(FFN_DIM/128, T/128), blk>>>(x1r, D, w1t, D, b1, h, FFN_DIM, D, 1.0f);
    hgemm<0,false><<<dim3(D/128, T/128), blk>>>(h, FFN_DIM, w2t, FFN_DIM, b2, y, D, FFN_DIM, 1.0f);
    ln_kernel<<<dim3(T), blk>>>(x1, y, ln2g, ln2b, xout, nullptr);
}

// round 12
// speedup vs baseline: 1.8335x; 1.0186x over previous
#include <cuda_runtime.h>
#include <cuda_fp16.h>
#include <math.h>
#include <stdint.h>

#define S 2048
#define BATCH 2
#define D 1024
#define H 16
#define FFN_DIM 4096
#define T (S*BATCH)
#define NEGV -1e9f
#define QKV_LD 3072

// ---------------- scratch (device globals; no allocation allowed) ----------------
__device__ __half g_qkv[(size_t)T*3*D];
__device__ __half g_ao[(size_t)T*D];
__device__ float  g_x1[(size_t)T*D];
__device__ __half g_x1r[(size_t)T*D];
__device__ float  g_y[(size_t)T*D];
__device__ __half g_h[(size_t)T*FFN_DIM];
__device__ float  g_attn[(size_t)BATCH*H*S*S];   // fallback buffers only
__device__ __half g_xr[(size_t)T*D];
__device__ __half g_wqkvt[(size_t)3*D*D];
__device__ __half g_wot[(size_t)D*D];
__device__ __half g_w1t[(size_t)D*FFN_DIM];
__device__ __half g_w2t[(size_t)D*FFN_DIM];
__device__ float  g_bqkv[3*D];

// ---------------- helpers ----------------
__device__ __forceinline__ void mma16(float* c, const uint32_t* a, const uint32_t* b) {
    asm("mma.sync.aligned.m16n8k16.row.col.f32.f16.f16.f32 "
        "{%0,%1,%2,%3},{%4,%5,%6,%7},{%8,%9},{%0,%1,%2,%3};"
        : "+f"(c[0]), "+f"(c[1]), "+f"(c[2]), "+f"(c[3])
        : "r"(a[0]), "r"(a[1]), "r"(a[2]), "r"(a[3]),
          "r"(b[0]), "r"(b[1]));
}

__device__ __forceinline__ void ldsm4(uint32_t& r0, uint32_t& r1, uint32_t& r2, uint32_t& r3,
                                      uint32_t addr) {
    asm volatile("ldmatrix.sync.aligned.m8n8.x4.shared.b16 {%0,%1,%2,%3}, [%4];"
                 : "=r"(r0), "=r"(r1), "=r"(r2), "=r"(r3) : "r"(addr));
}

__device__ __forceinline__ void ldsm4t(uint32_t& r0, uint32_t& r1, uint32_t& r2, uint32_t& r3,
                                       uint32_t addr) {
    asm volatile("ldmatrix.sync.aligned.m8n8.x4.trans.shared.b16 {%0,%1,%2,%3}, [%4];"
                 : "=r"(r0), "=r"(r1), "=r"(r2), "=r"(r3) : "r"(addr));
}

__device__ __forceinline__ void cpasync16(uint32_t dst, const void* src) {
    asm volatile("cp.async.cg.shared.global [%0], [%1], 16;" :: "r"(dst), "l"(src));
}

__device__ __forceinline__ int ch8(int r, int q) {   // 16B-chunk swizzle, 128B rows (== SW128)
    return r * 8 + (q ^ (r & 7));
}

__device__ __forceinline__ float gelu(float v) {
    return 0.5f * v * (1.0f + erff(v * 0.70710678118654752f));
}

// =====================================================================
// fp16 cp.async 3-stage GEMM, BK=64: C[M,N] = A[M,K]@B^T + bias (B [N][K]).
// BM=128, BN=128, 256 threads (8 warps, 2m x 4n). 128B rows, ch8 swizzle.
// Per stage: A 16KB + B 16KB. 3 stages = 96KB dynamic smem (2 CTAs/SM).
// EPI: 0=bias, 1=bias*scale, 2=gelu(bias), 3=QKV (scale cols < D only).
// OUTH: write __half else float.
// =====================================================================
#define HG_SMEM_BYTES (3 * 32768)

template<int EPI, bool OUTH>
__global__ __launch_bounds__(256, 2) void hgemm(
    const __half* __restrict__ A, long long lda,
    const __half* __restrict__ Bg, long long ldb,
    const float* __restrict__ bias,
    void* __restrict__ Cv, long long ldc,
    int K, float scale)
{
    extern __shared__ char smc[];
    const uint32_t smb = (uint32_t)__cvta_generic_to_shared(smc);

    const int tid  = threadIdx.x;
    const int lane = tid & 31;
    const int w    = tid >> 5;
    const int wm   = w & 1;
    const int wn   = w >> 1;
    const int m0   = blockIdx.y * 128;
    const int n0   = blockIdx.x * 128;

    float acc[4][4][4] = {};
    const int nt = K >> 6;

    const int fm = lane >> 3;
    const int fj = lane & 7;
    const int aRowBase = wm * 64 + (fm & 1) * 8 + fj;
    const int aKqOff   = fm >> 1;
    const int bTileOff = fm >> 1;
    const int bKqOff   = fm & 1;

    auto issue = [&](int t) {
        if (t < nt) {
            const uint32_t base = smb + (uint32_t)((t % 3) * 32768);
            const int k0 = t << 6;
            #pragma unroll
            for (int u = 0; u < 8; u++) {
                int cc = tid + u * 256;
                int row = cc >> 3, q = cc & 7;
                if (row < 128)
                    cpasync16(base + (uint32_t)(ch8(row, q) * 16),
                              A + (size_t)(m0 + row) * lda + k0 + q * 8);
                else
                    cpasync16(base + 16384u + (uint32_t)(ch8(row - 128, q) * 16),
                              Bg + (size_t)(n0 + row - 128) * ldb + k0 + q * 8);
            }
        }
        asm volatile("cp.async.commit_group;");
    };

    auto compute = [&](int buf) {
        const uint32_t aBase = smb + (uint32_t)(buf * 32768);
        const uint32_t bBase = aBase + 16384u;
        #pragma unroll
        for (int ks = 0; ks < 4; ks++) {
            uint32_t a[4][4];
            uint32_t b[4][2];
            const int akq = ks * 2 + aKqOff;
            const int bkq = ks * 2 + bKqOff;
            #pragma unroll
            for (int i = 0; i < 4; i++) {
                uint32_t addr = aBase + (uint32_t)(ch8(aRowBase + i * 16, akq) * 16);
                ldsm4(a[i][0], a[i][1], a[i][2], a[i][3], addr);
            }
            #pragma unroll
            for (int j2 = 0; j2 < 4; j2 += 2) {
                int tile = wn * 4 + j2 + bTileOff;
                uint32_t addr = bBase + (uint32_t)(ch8(tile * 8 + fj, bkq) * 16);
                ldsm4(b[j2][0], b[j2][1], b[j2 + 1][0], b[j2 + 1][1], addr);
            }
            #pragma unroll
            for (int i = 0; i < 4; i++)
                #pragma unroll
                for (int j = 0; j < 4; j++)
                    mma16(acc[i][j], a[i], b[j]);
        }
    };

    issue(0);
    issue(1);
    for (int t = 0; t < nt; t++) {
        asm volatile("cp.async.wait_group 1;");
        __syncthreads();
        issue(t + 2);
        compute(t % 3);
    }

    const float sc = (EPI == 1) ? scale : (EPI == 3 ? (n0 < D ? scale : 1.0f) : 1.0f);

    #pragma unroll
    for (int i = 0; i < 4; i++) {
        int r0 = m0 + wm * 64 + i * 16 + (lane >> 2);
        #pragma unroll
        for (int j = 0; j < 4; j++) {
            int col = n0 + wn * 32 + j * 8 + ((lane & 3) << 1);
            float2 bb = *(const float2*)&bias[col];
            float v0 = acc[i][j][0] + bb.x, v1 = acc[i][j][1] + bb.y;
            float v2 = acc[i][j][2] + bb.x, v3 = acc[i][j][3] + bb.y;
            if (EPI == 1 || EPI == 3) { v0 *= sc; v1 *= sc; v2 *= sc; v3 *= sc; }
            if (EPI == 2) { v0 = gelu(v0); v1 = gelu(v1); v2 = gelu(v2); v3 = gelu(v3); }
            if (OUTH) {
                __half* C = (__half*)Cv;
                *(__half2*)&C[(size_t)r0 * ldc + col]       = __floats2half2_rn(v0, v1);
                *(__half2*)&C[(size_t)(r0 + 8) * ldc + col] = __floats2half2_rn(v2, v3);
            } else {
                float* C = (float*)Cv;
                *(float2*)&C[(size_t)r0 * ldc + col]       = make_float2(v0, v1);
                *(float2*)&C[(size_t)(r0 + 8) * ldc + col] = make_float2(v2, v3);
            }
        }
    }
}

// =====================================================================
// Fused attention, fp16 (round-10, unchanged).
// =====================================================================
#define AF_SMEM_BYTES 106496

__global__ __launch_bounds__(256, 2) void attn_fused(
    const __half* __restrict__ qkv, const unsigned char* __restrict__ mask,
    float* __restrict__ probs, __half* __restrict__ aog)
{
    extern __shared__ char smc[];
    const int tid  = threadIdx.x;
    const int lane = tid & 31;
    const int w    = tid >> 5;
    const int wm   = w & 1;
    const int wn   = w >> 1;
    const int q0   = blockIdx.x * 128;
    const int z    = blockIdx.y;
    const int b    = z >> 4, hh = z & 15;
    const long long ld  = (long long)BATCH * QKV_LD;
    const long long ldo = (long long)BATCH * D;

    const __half* Q = qkv + (size_t)b * QKV_LD + hh * 64;
    const __half* K = Q + D;
    const __half* V = Q + 2 * D;
    float* P   = probs + (size_t)z * S * S;
    __half* AO = aog + (size_t)b * D + hh * 64;
    const unsigned char* MK = mask + (size_t)b * S;

    const uint32_t smb = (uint32_t)__cvta_generic_to_shared(smc);
    float* fmask = (float*)(smc + 98304);

    const int fm = lane >> 3;
    const int fj = lane & 7;
    const int aRowN    = w * 16 + (fm & 1) * 8 + fj;
    const int aRowBase = wm * 64 + (fm & 1) * 8 + fj;
    const int aKqOff   = fm >> 1;
    const int bTileOff = fm >> 1;
    const int bKqOff   = fm & 1;

    #pragma unroll
    for (int u = 0; u < 8; u++) {
        int i = tid + u * 256;
        fmask[i] = MK[i] ? NEGV : 0.0f;
    }

    #pragma unroll
    for (int u = 0; u < 4; u++) {
        int c = tid + u * 256;
        int row = c >> 3, kq = c & 7;
        cpasync16(smb + (uint32_t)(ch8(row, kq) * 16),
                  Q + (size_t)(q0 + row) * ld + kq * 8);
    }

    auto issueK = [&](int it) {
        if (it < 32) {
            const uint32_t kb = smb + 16384u + (uint32_t)((it % 3) * 8192);
            const int key0 = it * 64;
            #pragma unroll
            for (int u = 0; u < 2; u++) {
                int c = tid + u * 256;
                int key = c >> 3, kq = c & 7;
                cpasync16(kb + (uint32_t)(ch8(key, kq) * 16),
                          K + (size_t)(key0 + key) * ld + kq * 8);
            }
        }
        asm volatile("cp.async.commit_group;");
    };
    auto issueKV = [&](int it) {
        if (it < 32) {
            const uint32_t kb = smb + 16384u + (uint32_t)((it % 3) * 8192);
            const uint32_t vb = smb + 40960u + (uint32_t)((it % 3) * 8192);
            const int key0 = it * 64;
            #pragma unroll
            for (int u = 0; u < 2; u++) {
                int c = tid + u * 256;
                int key = c >> 3, kq = c & 7;
                cpasync16(kb + (uint32_t)(ch8(key, kq) * 16),
                          K + (size_t)(key0 + key) * ld + kq * 8);
                cpasync16(vb + (uint32_t)(ch8(key, kq) * 16),
                          V + (size_t)(key0 + key) * ld + kq * 8);
            }
        }
        asm volatile("cp.async.commit_group;");
    };

    auto score = [&](int buf, float (&acc)[8][4]) {
        #pragma unroll
        for (int j = 0; j < 8; j++)
            #pragma unroll
            for (int c = 0; c < 4; c++) acc[j][c] = 0.f;
        const uint32_t kb = smb + 16384u + (uint32_t)(buf * 8192);
        #pragma unroll
        for (int ks = 0; ks < 4; ks++) {
            uint32_t a[4];
            uint32_t bfr[8][2];
            {
                uint32_t addr = smb + (uint32_t)(ch8(aRowN, ks * 2 + aKqOff) * 16);
                ldsm4(a[0], a[1], a[2], a[3], addr);
            }
            #pragma unroll
            for (int j2 = 0; j2 < 8; j2 += 2) {
                int tile = j2 + bTileOff;
                uint32_t addr = kb + (uint32_t)(ch8(tile * 8 + fj, ks * 2 + bKqOff) * 16);
                ldsm4(bfr[j2][0], bfr[j2][1], bfr[j2 + 1][0], bfr[j2 + 1][1], addr);
            }
            #pragma unroll
            for (int j = 0; j < 8; j++)
                mma16(acc[j], a, bfr[j]);
        }
    };

    float acc[8][4];
    float m0 = -1e30f, m1 = -1e30f, s0 = 0.f, s1 = 0.f;

    issueK(0);
    issueK(1);
    for (int it = 0; it < 32; it++) {
        asm volatile("cp.async.wait_group 1;");
        __syncthreads();
        issueK(it + 2);
        score(it % 3, acc);

        float2 fmj[8];
        #pragma unroll
        for (int j = 0; j < 8; j++)
            fmj[j] = *(const float2*)&fmask[it * 64 + j * 8 + ((lane & 3) << 1)];

        float mt0 = -1e30f, mt1 = -1e30f;
        #pragma unroll
        for (int j = 0; j < 8; j++) {
            mt0 = fmaxf(mt0, fmaxf(acc[j][0] + fmj[j].x, acc[j][1] + fmj[j].y));
            mt1 = fmaxf(mt1, fmaxf(acc[j][2] + fmj[j].x, acc[j][3] + fmj[j].y));
        }
        mt0 = fmaxf(mt0, __shfl_xor_sync(0xffffffffu, mt0, 1));
        mt0 = fmaxf(mt0, __shfl_xor_sync(0xffffffffu, mt0, 2));
        mt1 = fmaxf(mt1, __shfl_xor_sync(0xffffffffu, mt1, 1));
        mt1 = fmaxf(mt1, __shfl_xor_sync(0xffffffffu, mt1, 2));

        float mn0 = fmaxf(m0, mt0), mn1 = fmaxf(m1, mt1);
        float c0 = __expf(m0 - mn0), c1 = __expf(m1 - mn1);
        float ls0 = 0.f, ls1 = 0.f;
        #pragma unroll
        for (int j = 0; j < 8; j++) {
            ls0 += __expf(acc[j][0] + fmj[j].x - mn0) + __expf(acc[j][1] + fmj[j].y - mn0);
            ls1 += __expf(acc[j][2] + fmj[j].x - mn1) + __expf(acc[j][3] + fmj[j].y - mn1);
        }
        ls0 += __shfl_xor_sync(0xffffffffu, ls0, 1);
        ls0 += __shfl_xor_sync(0xffffffffu, ls0, 2);
        ls1 += __shfl_xor_sync(0xffffffffu, ls1, 1);
        ls1 += __shfl_xor_sync(0xffffffffu, ls1, 2);

        s0 = s0 * c0 + ls0;
        s1 = s1 * c1 + ls1;
        m0 = mn0; m1 = mn1;
    }

    const float inv0 = 1.0f / s0;
    const float inv1 = 1.0f / s1;

    float O[4][2][4] = {};

    auto pv = [&](int t) {
        const uint32_t pb = smb + 65536u + (uint32_t)((t & 1) * 16384);
        const uint32_t vb = smb + 40960u + (uint32_t)((t % 3) * 8192);
        #pragma unroll
        for (int ks = 0; ks < 4; ks++) {
            uint32_t a[4][4];
            uint32_t bv[2][2];
            #pragma unroll
            for (int i = 0; i < 4; i++) {
                uint32_t addr = pb + (uint32_t)(ch8(aRowBase + i * 16, ks * 2 + aKqOff) * 16);
                ldsm4(a[i][0], a[i][1], a[i][2], a[i][3], addr);
            }
            {
                uint32_t addr = vb + (uint32_t)(ch8(16 * ks + (fm & 1) * 8 + fj,
                                                    wn * 2 + (fm >> 1)) * 16);
                ldsm4t(bv[0][0], bv[0][1], bv[1][0], bv[1][1], addr);
            }
            #pragma unroll
            for (int i = 0; i < 4; i++)
                #pragma unroll
                for (int j = 0; j < 2; j++)
                    mma16(O[i][j], a[i], bv[j]);
        }
    };

    issueKV(0);
    issueKV(1);
    for (int it = 0; it < 32; it++) {
        asm volatile("cp.async.wait_group 1;");
        __syncthreads();
        score(it % 3, acc);

        const int key0 = it * 64;
        const int r0l = w * 16 + (lane >> 2);
        const int r1l = r0l + 8;
        char* pB = smc + 65536 + (it & 1) * 16384;
        #pragma unroll
        for (int j = 0; j < 8; j++) {
            float2 fmv = *(const float2*)&fmask[key0 + j * 8 + ((lane & 3) << 1)];
            float p0 = __expf(acc[j][0] + fmv.x - m0) * inv0;
            float p1 = __expf(acc[j][1] + fmv.y - m0) * inv0;
            float p2 = __expf(acc[j][2] + fmv.x - m1) * inv1;
            float p3 = __expf(acc[j][3] + fmv.y - m1) * inv1;
            int keyloc = j * 8 + ((lane & 3) << 1);
            __stcs((float2*)&P[(size_t)(q0 + r0l) * S + key0 + keyloc], make_float2(p0, p1));
            __stcs((float2*)&P[(size_t)(q0 + r1l) * S + key0 + keyloc], make_float2(p2, p3));
            *(__half2*)(pB + ch8(r0l, j) * 16 + (lane & 3) * 4) = __floats2half2_rn(p0, p1);
            *(__half2*)(pB + ch8(r1l, j) * 16 + (lane & 3) * 4) = __floats2half2_rn(p2, p3);
        }

        if (it > 0) pv(it - 1);
        __syncthreads();
        issueKV(it + 2);
    }
    asm volatile("cp.async.wait_group 0;");
    pv(31);

    #pragma unroll
    for (int i = 0; i < 4; i++) {
        int r0 = q0 + wm * 64 + i * 16 + (lane >> 2);
        #pragma unroll
        for (int j = 0; j < 2; j++) {
            int col = wn * 16 + j * 8 + ((lane & 3) << 1);
            *(__half2*)&AO[(size_t)r0 * ldo + col] =
                __floats2half2_rn(O[i][j][0], O[i][j][1]);
            *(__half2*)&AO[(size_t)(r0 + 8) * ldo + col] =
                __floats2half2_rn(O[i][j][2], O[i][j][3]);
        }
    }
}

// ---------------- fused pre-pass (round-10, unchanged) ----------------
__device__ __forceinline__ void tile_transpose_h(
    const float* __restrict__ in, __half* __restrict__ out,
    int K, int N, int t, int tx, int ty)
{
    __shared__ float tile[32][33];
    int nt = N / 32;
    int n = (t % nt) * 32 + tx;
    int k = (t / nt) * 32 + ty;
    #pragma unroll
    for (int i = 0; i < 32; i += 8)
        tile[ty + i][tx] = in[(size_t)(k + i) * N + n];
    __syncthreads();
    int n2 = (t % nt) * 32 + ty;
    int k2 = (t / nt) * 32 + tx;
    #pragma unroll
    for (int i = 0; i < 32; i += 8)
        out[(size_t)(n2 + i) * K + k2] = __float2half_rn(tile[tx][ty + i]);
}

__global__ void prep_all(
    const float* __restrict__ Wq, const float* __restrict__ Wk,
    const float* __restrict__ Wv, const float* __restrict__ Wo,
    const float* __restrict__ W1, const float* __restrict__ W2,
    const float* __restrict__ x,
    const float* __restrict__ bq, const float* __restrict__ bk,
    const float* __restrict__ bv,
    __half* __restrict__ wqkvt, __half* __restrict__ wot,
    __half* __restrict__ w1t, __half* __restrict__ w2t,
    __half* __restrict__ xr, float* __restrict__ bqkv)
{
    const int bz = blockIdx.x;
    const int tx = threadIdx.x, ty = threadIdx.y;
    const int tid = ty * 32 + tx;

    if (bz < 1024) {
        tile_transpose_h(Wq, wqkvt, D, D, bz, tx, ty);
    } else if (bz < 2048) {
        tile_transpose_h(Wk, wqkvt + (size_t)D * D, D, D, bz - 1024, tx, ty);
    } else if (bz < 3072) {
        tile_transpose_h(Wv, wqkvt + (size_t)2 * D * D, D, D, bz - 2048, tx, ty);
    } else if (bz < 4096) {
        tile_transpose_h(Wo, wot, D, D, bz - 3072, tx, ty);
    } else if (bz < 8192) {
        tile_transpose_h(W1, w1t, D, FFN_DIM, bz - 4096, tx, ty);
    } else if (bz < 12288) {
        tile_transpose_h(W2, w2t, FFN_DIM, D, bz - 8192, tx, ty);
    } else if (bz < 13312) {
        int base = (bz - 12288) * 1024;
        #pragma unroll
        for (int u = 0; u < 4; u++) {
            int i = base + tid + u * 256;
            float4 v = ((const float4*)x)[i];
            ((__half2*)xr)[2*i]   = __floats2half2_rn(v.x, v.y);
            ((__half2*)xr)[2*i+1] = __floats2half2_rn(v.z, v.w);
        }
    } else {
        int i = (bz - 13312) * 256 + tid;
        bqkv[i] = (i < D) ? bq[i] : (i < 2*D) ? bk[i - D] : bv[i - 2*D];
    }
}

// ---------------- layernorm (round-10, unchanged) ----------------
__global__ __launch_bounds__(256) void ln_kernel(
    const float* __restrict__ resid, const float* __restrict__ y,
    const float* __restrict__ g, const float* __restrict__ beta,
    float* __restrict__ out, __half* __restrict__ out_r)
{
    const int row = blockIdx.x;
    const int tid = threadIdx.x;
    float4 a = ((const float4*)(resid + (size_t)row * D))[tid];
    float4 c = ((const float4*)(y + (size_t)row * D))[tid];
    float v0 = a.x + c.x, v1 = a.y + c.y, v2 = a.z + c.z, v3 = a.w + c.w;

    __shared__ float sh[256], sh2[256];
    sh[tid]  = v0 + v1 + v2 + v3;
    sh2[tid] = v0*v0 + v1*v1 + v2*v2 + v3*v3;
    __syncthreads();
    for (int st = 128; st > 0; st >>= 1) {
        if (tid < st) { sh[tid] += sh[tid + st]; sh2[tid] += sh2[tid + st]; }
        __syncthreads();
    }
    float mean = sh[0] * (1.0f / D);
    float var  = sh2[0] * (1.0f / D) - mean * mean;
    float rstd = rsqrtf(var + 1e-5f);

    float4 g4 = ((const float4*)g)[tid];
    float4 b4 = ((const float4*)beta)[tid];
    float4 o;
    o.x = (v0 - mean) * rstd * g4.x + b4.x;
    o.y = (v1 - mean) * rstd * g4.y + b4.y;
    o.z = (v2 - mean) * rstd * g4.z + b4.z;
    o.w = (v3 - mean) * rstd * g4.w + b4.w;
    ((float4*)(out + (size_t)row * D))[tid] = o;
    if (out_r) {
        __half2* hr = (__half2*)(out_r + (size_t)row * D);
        hr[2*tid]   = __floats2half2_rn(o.x, o.y);
        hr[2*tid+1] = __floats2half2_rn(o.z, o.w);
    }
}

// ---------------- launcher ----------------
extern "C" void kernel_launch(void* const* d_in, const int* in_sizes, int n_in,
                              void* d_out, int out_size)
{
    const float* x    = (const float*)d_in[0];
    const unsigned char* mask = (const unsigned char*)d_in[1];
    const float* Wq   = (const float*)d_in[2];
    const float* bq   = (const float*)d_in[3];
    const float* Wk   = (const float*)d_in[4];
    const float* bk   = (const float*)d_in[5];
    const float* Wv   = (const float*)d_in[6];
    const float* bv   = (const float*)d_in[7];
    const float* Wo   = (const float*)d_in[8];
    const float* bo   = (const float*)d_in[9];
    const float* ln1g = (const float*)d_in[10];
    const float* ln1b = (const float*)d_in[11];
    const float* W1   = (const float*)d_in[12];
    const float* b1   = (const float*)d_in[13];
    const float* W2   = (const float*)d_in[14];
    const float* b2   = (const float*)d_in[15];
    const float* ln2g = (const float*)d_in[16];
    const float* ln2b = (const float*)d_in[17];

    __half *qkv, *ao, *x1r, *h, *xr, *wqkvt, *wot, *w1t, *w2t;
    float *x1, *y, *attn, *bqkv;
    cudaGetSymbolAddress((void**)&qkv, g_qkv);
    cudaGetSymbolAddress((void**)&ao,  g_ao);
    cudaGetSymbolAddress((void**)&x1,  g_x1);
    cudaGetSymbolAddress((void**)&x1r, g_x1r);
    cudaGetSymbolAddress((void**)&y,   g_y);
    cudaGetSymbolAddress((void**)&h,   g_h);
    cudaGetSymbolAddress((void**)&attn, g_attn);
    cudaGetSymbolAddress((void**)&xr,  g_xr);
    cudaGetSymbolAddress((void**)&wqkvt, g_wqkvt);
    cudaGetSymbolAddress((void**)&wot, g_wot);
    cudaGetSymbolAddress((void**)&w1t, g_w1t);
    cudaGetSymbolAddress((void**)&w2t, g_w2t);
    cudaGetSymbolAddress((void**)&bqkv, g_bqkv);

    const long long X  = (long long)T * D;
    const long long AW = (long long)BATCH * H * (long long)S * S;
    float* xout;
    float* attnout;
    if ((long long)out_size >= X + AW) {
        xout = (float*)d_out;
        attnout = (float*)d_out + X;
    } else if ((long long)out_size == AW) {
        attnout = (float*)d_out;
        xout = attn;
    } else {
        xout = (float*)d_out;
        attnout = attn;
    }

    static int attr_set = 0;
    if (!attr_set) {
        cudaFuncSetAttribute(attn_fused,
                             cudaFuncAttributeMaxDynamicSharedMemorySize, AF_SMEM_BYTES);
        cudaFuncSetAttribute(hgemm<3,true>,
                             cudaFuncAttributeMaxDynamicSharedMemorySize, HG_SMEM_BYTES);
        cudaFuncSetAttribute(hgemm<0,false>,
                             cudaFuncAttributeMaxDynamicSharedMemorySize, HG_SMEM_BYTES);
        cudaFuncSetAttribute(hgemm<2,true>,
                             cudaFuncAttributeMaxDynamicSharedMemorySize, HG_SMEM_BYTES);
        attr_set = 1;
    }

    dim3 blk(256);
    const float scaling = 0.125f;

    // ---- fused pre-pass ----
    prep_all<<<dim3(13324), dim3(32, 8)>>>(Wq, Wk, Wv, Wo, W1, W2, x,
                                           bq, bk, bv,
                                           wqkvt, wot, w1t, w2t, xr, bqkv);

    // ---- merged QKV projection ----
    hgemm<3,true><<<dim3(3*D/128, T/128), blk, HG_SMEM_BYTES>>>(
        xr, D, wqkvt, D, bqkv, qkv, QKV_LD, D, scaling);

    // ---- fused attention ----
    attn_fused<<<dim3(S/128, BATCH*H), blk, AF_SMEM_BYTES>>>(qkv, mask, attnout, ao);

    // ---- O-proj + LN1 ----
    hgemm<0,false><<<dim3(D/128, T/128), blk, HG_SMEM_BYTES>>>(
        ao, D, wot, D, bo, y, D, D, 1.0f);
    ln_kernel<<<dim3(T), blk>>>(x, y, ln1g, ln1b, x1, x1r);

    // ---- FFN + LN2 ----
    hgemm<2,true><<<dim3(FFN_DIM/128, T/128), blk, HG_SMEM_BYTES>>>(
        x1r, D, w1t, D, b1, h, FFN_DIM, D, 1.0f);
    hgemm<0,false><<<dim3(D/128, T/128), blk, HG_SMEM_BYTES>>>(
        h, FFN_DIM, w2t, FFN_DIM, b2, y, D, FFN_DIM, 1.0f);
    ln_kernel<<<dim3(T), blk>>>(x1, y, ln2g, ln2b, xout, nullptr);
}